// round 4
// baseline (speedup 1.0000x reference)
#include <cuda_runtime.h>
#include <cuda_bf16.h>
#include <cstdint>

#define BB 2
#define SS 2048
#define HH 1024
#define NH 16
#define HD 64
#define ZT (BB * NH)
#define EROWS 4224   // 4095 used + zero pad

// fp32 scratch (v stays fp32; pv converts in-kernel)
__device__ float g_v[ZT * SS * HD];
// split-bf16 operands
__device__ __nv_bfloat16 g_qh[ZT * SS * HD], g_ql[ZT * SS * HD];
__device__ __nv_bfloat16 g_kh[ZT * SS * HD], g_kl[ZT * SS * HD];
__device__ __nv_bfloat16 g_eh[EROWS * HD], g_el[EROWS * HD];

#define SW128(o) ((o) ^ (((o) >> 3) & 0x70))

__device__ __forceinline__ uint32_t smem_u32(const void* p) {
    uint32_t a;
    asm("{ .reg .u64 t; cvta.to.shared.u64 t, %1; cvt.u32.u64 %0, t; }"
        : "=r"(a) : "l"(p));
    return a;
}
__device__ __forceinline__ void ldsm4(uint32_t r[4], uint32_t addr) {
    asm volatile("ldmatrix.sync.aligned.m8n8.x4.shared.b16 {%0,%1,%2,%3}, [%4];"
        : "=r"(r[0]), "=r"(r[1]), "=r"(r[2]), "=r"(r[3]) : "r"(addr));
}
__device__ __forceinline__ void ldsm4t(uint32_t r[4], uint32_t addr) {
    asm volatile("ldmatrix.sync.aligned.m8n8.x4.trans.shared.b16 {%0,%1,%2,%3}, [%4];"
        : "=r"(r[0]), "=r"(r[1]), "=r"(r[2]), "=r"(r[3]) : "r"(addr));
}
__device__ __forceinline__ void mma_bf16(float c[4], const uint32_t a[4],
                                         const uint32_t b[2]) {
    asm volatile(
        "mma.sync.aligned.m16n8k16.row.col.f32.bf16.bf16.f32 "
        "{%0,%1,%2,%3}, {%4,%5,%6,%7}, {%8,%9}, {%0,%1,%2,%3};"
        : "+f"(c[0]), "+f"(c[1]), "+f"(c[2]), "+f"(c[3])
        : "r"(a[0]), "r"(a[1]), "r"(a[2]), "r"(a[3]), "r"(b[0]), "r"(b[1]));
}
__device__ __forceinline__ void split8(const float4& f0, const float4& f1,
                                       uint4& h4, uint4& l4) {
    float f[8] = {f0.x, f0.y, f0.z, f0.w, f1.x, f1.y, f1.z, f1.w};
    __nv_bfloat162* hp = (__nv_bfloat162*)&h4;
    __nv_bfloat162* lp = (__nv_bfloat162*)&l4;
#pragma unroll
    for (int j = 0; j < 4; j++) {
        __nv_bfloat16 a = __float2bfloat16(f[2 * j]);
        __nv_bfloat16 b = __float2bfloat16(f[2 * j + 1]);
        __nv_bfloat16 al = __float2bfloat16(f[2 * j] - __bfloat162float(a));
        __nv_bfloat16 bl = __float2bfloat16(f[2 * j + 1] - __bfloat162float(b));
        hp[j] = __halves2bfloat162(a, b);
        lp[j] = __halves2bfloat162(al, bl);
    }
}

// ---------------------------------------------------------------------------
// Kernel 1: fused QKV projection. Writes q,k as split-bf16 (hi/lo), v as fp32.
// ---------------------------------------------------------------------------
__global__ __launch_bounds__(256) void qkv_kernel(
    const float* __restrict__ A, const float* __restrict__ W,
    const float* __restrict__ bias)
{
    __shared__ float As[8][128];
    __shared__ float Ws[8][128];
    const int tid = threadIdx.x;
    const int bx = blockIdx.x, by = blockIdx.y;
    const int tx = tid % 16, ty = tid / 16;

    float acc[8][8];
#pragma unroll
    for (int i = 0; i < 8; i++)
#pragma unroll
        for (int j = 0; j < 8; j++) acc[i][j] = 0.f;

    const int ar = tid >> 1;
    const int ac = (tid & 1) * 4;
    const int wr = tid >> 5;
    const int wc = (tid & 31) * 4;

    const float* Aptr = A + (size_t)(by * 128 + ar) * HH + ac;
    const float* Wptr = W + (size_t)wr * 3072 + bx * 128 + wc;

    for (int kt = 0; kt < HH / 8; kt++) {
        float4 av = *(const float4*)(Aptr + kt * 8);
        float4 wv = *(const float4*)(Wptr + (size_t)kt * 8 * 3072);
        As[ac + 0][ar] = av.x; As[ac + 1][ar] = av.y;
        As[ac + 2][ar] = av.z; As[ac + 3][ar] = av.w;
        *(float4*)&Ws[wr][wc] = wv;
        __syncthreads();
#pragma unroll
        for (int k = 0; k < 8; k++) {
            float a[8], b[8];
#pragma unroll
            for (int i = 0; i < 8; i++) a[i] = As[k][ty * 8 + i];
#pragma unroll
            for (int j = 0; j < 8; j++) b[j] = Ws[k][tx * 8 + j];
#pragma unroll
            for (int i = 0; i < 8; i++)
#pragma unroll
                for (int j = 0; j < 8; j++) acc[i][j] += a[i] * b[j];
        }
        __syncthreads();
    }

    const int n0 = bx * 128 + tx * 8;
    const int which = n0 / 1024;
    const int h = (n0 % 1024) / 64;
    const int d0 = n0 % 64;
    float bv[8];
#pragma unroll
    for (int j = 0; j < 8; j++) bv[j] = bias[n0 + j];

#pragma unroll
    for (int i = 0; i < 8; i++) {
        int m = by * 128 + ty * 8 + i;
        int b = m / SS, s = m % SS;
        size_t off = ((size_t)(b * NH + h) * SS + s) * HD + d0;
        float vv[8];
#pragma unroll
        for (int j = 0; j < 8; j++) vv[j] = acc[i][j] + bv[j];

        if (which == 2) {
            float* p = g_v + off;
            *(float4*)p = make_float4(vv[0], vv[1], vv[2], vv[3]);
            *(float4*)(p + 4) = make_float4(vv[4], vv[5], vv[6], vv[7]);
        } else {
            __nv_bfloat16* dh = which ? g_kh : g_qh;
            __nv_bfloat16* dl = which ? g_kl : g_ql;
            uint4 uh, ul;
            split8(make_float4(vv[0], vv[1], vv[2], vv[3]),
                   make_float4(vv[4], vv[5], vv[6], vv[7]), uh, ul);
            *(uint4*)(dh + off) = uh;
            *(uint4*)(dl + off) = ul;
        }
    }
}

// ---------------------------------------------------------------------------
// Kernel 1b: split dist_emb into bf16 hi/lo (zero-padded rows beyond 4094)
// ---------------------------------------------------------------------------
__global__ __launch_bounds__(256) void split_e_kernel(const float* __restrict__ dist_emb)
{
    int i = blockIdx.x * 256 + threadIdx.x;
    if (i >= EROWS * HD) return;
    float e = (i < 4095 * HD) ? dist_emb[i] : 0.f;
    __nv_bfloat16 h = __float2bfloat16(e);
    g_eh[i] = h;
    g_el[i] = __float2bfloat16(e - __bfloat162float(h));
}

// ---------------------------------------------------------------------------
// Kernel 2: score kernel on warp MMA (HMMA bf16, split hi/lo, 3 terms).
// Per block: (z, 64 l x 64 r). 10 warps:
//   warps 0-5 (G1): C1[64x192] = Q @ [K | E_win]^T  (S cols 0-63, QE j 0-127)
//   warps 6-9 (G2): C2[64x128] = K @ E_win^T        (KE j 0-127)
// out[u,v] = 0.125*S[u,v] + QE[u, 63+u-v] + KE[v, 63+u-v] + mask[v]
// ---------------------------------------------------------------------------
#define OFF_QH 0
#define OFF_QL 8192
#define OFF_KH 16384
#define OFF_KL 24576
#define OFF_EH 32768
#define OFF_EL 49152
// staging (overlays operands after compute)
#define OFF_SS 0                 // 64*66*4  = 16896
#define OFF_QES 16896            // 64*130*4 = 33280
#define OFF_KES 50176            // 64*130*4 = 33280 -> 83456
#define OFF_MASK 83456
#define SC_SMEM 83968

__global__ __launch_bounds__(320) void score_mma_kernel(
    const float* __restrict__ mask, float* __restrict__ probs)
{
    extern __shared__ char smem[];
    const uint32_t sb = smem_u32(smem);
    const int tid = threadIdx.x, wid = tid >> 5, lane = tid & 31;
    const int z = blockIdx.z;
    const int l0 = blockIdx.y * 64, r0 = blockIdx.x * 64;
    const int base2 = l0 - r0 + 1984;

    // ---- loads ----
    if (tid < 64)
        ((float*)(smem + OFF_MASK))[tid] = mask[(z / NH) * SS + r0 + tid];
    for (int i = tid; i < 512; i += 320) {
        int row = i >> 3, c = i & 7;
        uint32_t so = SW128((uint32_t)(row * 128 + c * 16));
        size_t gq = ((size_t)z * SS + l0 + row) * HD + c * 8;
        size_t gk = ((size_t)z * SS + r0 + row) * HD + c * 8;
        *(uint4*)(smem + OFF_QH + so) = *(const uint4*)(g_qh + gq);
        *(uint4*)(smem + OFF_QL + so) = *(const uint4*)(g_ql + gq);
        *(uint4*)(smem + OFF_KH + so) = *(const uint4*)(g_kh + gk);
        *(uint4*)(smem + OFF_KL + so) = *(const uint4*)(g_kl + gk);
    }
    for (int i = tid; i < 1024; i += 320) {
        int row = i >> 3, c = i & 7;
        uint32_t so = SW128((uint32_t)(row * 128 + c * 16));
        size_t ge = (size_t)(base2 + row) * HD + c * 8;
        *(uint4*)(smem + OFF_EH + so) = *(const uint4*)(g_eh + ge);
        *(uint4*)(smem + OFF_EL + so) = *(const uint4*)(g_el + ge);
    }
    __syncthreads();

    // ---- warp roles ----
    int m0, nb;
    uint32_t aH, aL, bH, bL;
    if (wid < 6) {
        m0 = (wid & 1) * 32;
        int ncb = wid >> 1;
        aH = sb + OFF_QH; aL = sb + OFF_QL;
        if (ncb == 0) { bH = sb + OFF_KH; bL = sb + OFF_KL; nb = 0; }
        else          { bH = sb + OFF_EH; bL = sb + OFF_EL; nb = (ncb - 1) * 64; }
    } else {
        int w = wid - 6;
        m0 = (w & 1) * 32;
        aH = sb + OFF_KH; aL = sb + OFF_KL;
        bH = sb + OFF_EH; bL = sb + OFF_EL;
        nb = (w >> 1) * 64;
    }

    float acc[2][8][4];
#pragma unroll
    for (int i = 0; i < 2; i++)
#pragma unroll
        for (int j = 0; j < 8; j++)
#pragma unroll
            for (int c = 0; c < 4; c++) acc[i][j][c] = 0.f;

    const int aRow = (lane & 7) + ((lane >> 3) & 1) * 8;
    const int aBx = (lane >> 4) * 16;
    const int bRow = (lane & 7) + (lane >> 4) * 8;
    const int bBx = ((lane >> 3) & 1) * 16;

#pragma unroll
    for (int ks = 0; ks < 4; ks++) {
        const int kb = ks * 32;
        uint32_t AH[2][4], AL[2][4], BH[4][4], BL[4][4];
#pragma unroll
        for (int mf = 0; mf < 2; mf++) {
            uint32_t off = SW128((uint32_t)((m0 + mf * 16 + aRow) * 128 + kb + aBx));
            ldsm4(AH[mf], aH + off);
            ldsm4(AL[mf], aL + off);
        }
#pragma unroll
        for (int nf = 0; nf < 4; nf++) {
            uint32_t off = SW128((uint32_t)((nb + nf * 16 + bRow) * 128 + kb + bBx));
            ldsm4(BH[nf], bH + off);
            ldsm4(BL[nf], bL + off);
        }
#pragma unroll
        for (int mf = 0; mf < 2; mf++)
#pragma unroll
            for (int nf = 0; nf < 8; nf++) {
                const uint32_t* bh = &BH[nf >> 1][(nf & 1) * 2];
                const uint32_t* bl = &BL[nf >> 1][(nf & 1) * 2];
                mma_bf16(acc[mf][nf], AH[mf], bh);
                mma_bf16(acc[mf][nf], AH[mf], bl);
                mma_bf16(acc[mf][nf], AL[mf], bh);
            }
    }
    __syncthreads();

    // ---- stage accumulators ----
    {
        float* sp; int stride, cbase;
        if (wid < 2)      { sp = (float*)(smem + OFF_SS);  stride = 66;  cbase = 0; }
        else if (wid < 6) { sp = (float*)(smem + OFF_QES); stride = 130; cbase = (wid >> 1) * 64 - 64; }
        else              { sp = (float*)(smem + OFF_KES); stride = 130; cbase = nb; }
        const int r = lane >> 2, c2 = 2 * (lane & 3);
#pragma unroll
        for (int mf = 0; mf < 2; mf++) {
            int u = m0 + mf * 16 + r;
#pragma unroll
            for (int nf = 0; nf < 8; nf++) {
                int cc = cbase + nf * 8 + c2;
                *(float2*)&sp[u * stride + cc] =
                    make_float2(acc[mf][nf][0], acc[mf][nf][1]);
                *(float2*)&sp[(u + 8) * stride + cc] =
                    make_float2(acc[mf][nf][2], acc[mf][nf][3]);
            }
        }
    }
    __syncthreads();

    // ---- gather + write ----
    if (tid < 256) {
        const float* Ss  = (const float*)(smem + OFF_SS);
        const float* QEs = (const float*)(smem + OFF_QES);
        const float* KEs = (const float*)(smem + OFF_KES);
        const float* msk = (const float*)(smem + OFF_MASK);
        const int u = tid >> 2;
        const int v0 = (tid & 3) * 16;
        float* orow = probs + ((size_t)z * SS + l0 + u) * SS + r0;
#pragma unroll
        for (int g = 0; g < 4; g++) {
            float4 o;
            float* po = (float*)&o;
#pragma unroll
            for (int c = 0; c < 4; c++) {
                int v = v0 + g * 4 + c;
                int j = u - v + 63;
                po[c] = 0.125f * Ss[u * 66 + v] + QEs[u * 130 + j]
                      + KEs[v * 130 + j] + msk[v];
            }
            *(float4*)(orow + v0 + g * 4) = o;
        }
    }
}

// ---------------------------------------------------------------------------
// Kernel 3: in-place row softmax over 2048 elements.
// ---------------------------------------------------------------------------
__global__ __launch_bounds__(256) void softmax_kernel(float* __restrict__ probs)
{
    __shared__ float red[256];
    const int tid = threadIdx.x;
    float4* p = (float4*)(probs + (size_t)blockIdx.x * SS);

    float4 x0 = p[tid];
    float4 x1 = p[tid + 256];

    float m = fmaxf(fmaxf(fmaxf(x0.x, x0.y), fmaxf(x0.z, x0.w)),
                    fmaxf(fmaxf(x1.x, x1.y), fmaxf(x1.z, x1.w)));
    red[tid] = m;
    __syncthreads();
#pragma unroll
    for (int s = 128; s > 0; s >>= 1) {
        if (tid < s) red[tid] = fmaxf(red[tid], red[tid + s]);
        __syncthreads();
    }
    m = red[0];
    __syncthreads();

    x0.x = __expf(x0.x - m); x0.y = __expf(x0.y - m);
    x0.z = __expf(x0.z - m); x0.w = __expf(x0.w - m);
    x1.x = __expf(x1.x - m); x1.y = __expf(x1.y - m);
    x1.z = __expf(x1.z - m); x1.w = __expf(x1.w - m);

    float sum = (x0.x + x0.y) + (x0.z + x0.w) + (x1.x + x1.y) + (x1.z + x1.w);
    red[tid] = sum;
    __syncthreads();
#pragma unroll
    for (int s = 128; s > 0; s >>= 1) {
        if (tid < s) red[tid] += red[tid + s];
        __syncthreads();
    }
    float inv = 1.f / red[0];

    x0.x *= inv; x0.y *= inv; x0.z *= inv; x0.w *= inv;
    x1.x *= inv; x1.y *= inv; x1.z *= inv; x1.w *= inv;
    p[tid] = x0;
    p[tid + 256] = x1;
}

// ---------------------------------------------------------------------------
// Kernel 4: ctx = probs @ v on warp MMA (split bf16, 3 terms).
// Per block: (z, 128 l). Loop r in 64-chunks; convert P,V to bf16 hi/lo in
// smem; A = P (ldmatrix), B = V via ldmatrix.trans.
// ---------------------------------------------------------------------------
#define PVO_PH 0
#define PVO_PL 16384
#define PVO_VH 32768
#define PVO_VL 40960
#define PV_SMEM 49152

__global__ __launch_bounds__(256) void pv_mma_kernel(
    const float* __restrict__ probs, float* __restrict__ ctx)
{
    extern __shared__ char smem[];
    const uint32_t sb = smem_u32(smem);
    const int tid = threadIdx.x, wid = tid >> 5, lane = tid & 31;
    const int z = blockIdx.y;
    const int l0 = blockIdx.x * 128;
    const int m0 = (wid >> 1) * 32, d0 = (wid & 1) * 32;

    float acc[2][4][4];
#pragma unroll
    for (int i = 0; i < 2; i++)
#pragma unroll
        for (int j = 0; j < 4; j++)
#pragma unroll
            for (int c = 0; c < 4; c++) acc[i][j][c] = 0.f;

    const int aRow = (lane & 7) + ((lane >> 3) & 1) * 8;
    const int aBx = (lane >> 4) * 16;

    const int prow = tid >> 1, prh = (tid & 1) * 32;

    for (int rt = 0; rt < 32; rt++) {
        const int r0c = rt * 64;
        // convert P tile [128 x 64]
        {
            const float* pg = probs + ((size_t)z * SS + l0 + prow) * SS + r0c + prh;
#pragma unroll
            for (int g = 0; g < 4; g++) {
                float4 f0 = *(const float4*)(pg + g * 8);
                float4 f1 = *(const float4*)(pg + g * 8 + 4);
                uint4 h, l;
                split8(f0, f1, h, l);
                uint32_t so = SW128((uint32_t)(prow * 128 + (prh + g * 8) * 2));
                *(uint4*)(smem + PVO_PH + so) = h;
                *(uint4*)(smem + PVO_PL + so) = l;
            }
        }
        // convert V tile [64 x 64]
        if (tid < 128) {
            const int vr = tid >> 1, vdh = (tid & 1) * 32;
            const float* vg = g_v + ((size_t)z * SS + r0c + vr) * HD + vdh;
#pragma unroll
            for (int g = 0; g < 4; g++) {
                float4 f0 = *(const float4*)(vg + g * 8);
                float4 f1 = *(const float4*)(vg + g * 8 + 4);
                uint4 h, l;
                split8(f0, f1, h, l);
                uint32_t so = SW128((uint32_t)(vr * 128 + (vdh + g * 8) * 2));
                *(uint4*)(smem + PVO_VH + so) = h;
                *(uint4*)(smem + PVO_VL + so) = l;
            }
        }
        __syncthreads();

#pragma unroll
        for (int ks = 0; ks < 4; ks++) {
            const int kb = ks * 32;
            uint32_t AH[2][4], AL[2][4], BH[2][4], BL[2][4];
#pragma unroll
            for (int mf = 0; mf < 2; mf++) {
                uint32_t off = SW128((uint32_t)((m0 + mf * 16 + aRow) * 128 + kb + aBx));
                ldsm4(AH[mf], sb + PVO_PH + off);
                ldsm4(AL[mf], sb + PVO_PL + off);
            }
#pragma unroll
            for (int nt = 0; nt < 2; nt++) {
                uint32_t off = SW128((uint32_t)((ks * 16 + aRow) * 128
                                                + (d0 + nt * 16) * 2 + aBx));
                ldsm4t(BH[nt], sb + PVO_VH + off);
                ldsm4t(BL[nt], sb + PVO_VL + off);
            }
#pragma unroll
            for (int mf = 0; mf < 2; mf++)
#pragma unroll
                for (int nf = 0; nf < 4; nf++) {
                    const uint32_t* bh = &BH[nf >> 1][(nf & 1) * 2];
                    const uint32_t* bl = &BL[nf >> 1][(nf & 1) * 2];
                    mma_bf16(acc[mf][nf], AH[mf], bh);
                    mma_bf16(acc[mf][nf], AH[mf], bl);
                    mma_bf16(acc[mf][nf], AL[mf], bh);
                }
        }
        __syncthreads();
    }

    // write ctx
    const int b = z / NH, h = z % NH;
    const int r = lane >> 2, c2 = 2 * (lane & 3);
#pragma unroll
    for (int mf = 0; mf < 2; mf++) {
        int l = l0 + m0 + mf * 16 + r;
#pragma unroll
        for (int nf = 0; nf < 4; nf++) {
            int d = d0 + nf * 8 + c2;
            float* o = ctx + ((size_t)b * SS + l) * HH + h * HD + d;
            *(float2*)o = make_float2(acc[mf][nf][0], acc[mf][nf][1]);
            *(float2*)(o + (size_t)8 * HH) = make_float2(acc[mf][nf][2], acc[mf][nf][3]);
        }
    }
}

// ---------------------------------------------------------------------------
extern "C" void kernel_launch(void* const* d_in, const int* in_sizes, int n_in,
                              void* d_out, int out_size)
{
    const float* hidden   = (const float*)d_in[0];
    const float* mask     = (const float*)d_in[1];
    const float* qkv_w    = (const float*)d_in[2];
    const float* qkv_b    = (const float*)d_in[3];
    const float* dist_emb = (const float*)d_in[4];

    float* out = (float*)d_out;
    float* ctx = out;
    float* probs = out + (size_t)BB * SS * HH;

    // 1) QKV projection -> split-bf16 q,k + fp32 v
    qkv_kernel<<<dim3(3072 / 128, 4096 / 128), 256>>>(hidden, qkv_w, qkv_b);

    // 1b) split dist_emb into bf16 hi/lo
    split_e_kernel<<<(EROWS * HD + 255) / 256, 256>>>(dist_emb);

    // 2) warp-MMA scores (+ bias + mask) -> probs buffer (raw)
    cudaFuncSetAttribute(score_mma_kernel,
                         cudaFuncAttributeMaxDynamicSharedMemorySize, SC_SMEM);
    score_mma_kernel<<<dim3(SS / 64, SS / 64, ZT), 320, SC_SMEM>>>(mask, probs);

    // 3) softmax in place
    softmax_kernel<<<ZT * SS, 256>>>(probs);

    // 4) ctx = probs @ v (warp MMA)
    cudaFuncSetAttribute(pv_mma_kernel,
                         cudaFuncAttributeMaxDynamicSharedMemorySize, PV_SMEM);
    pv_mma_kernel<<<dim3(SS / 128, ZT), 256, PV_SMEM>>>(probs, ctx);
}

// round 6
// speedup vs baseline: 1.1230x; 1.1230x over previous
#include <cuda_runtime.h>
#include <cuda_bf16.h>
#include <cstdint>

#define BB 2
#define SS 2048
#define HH 1024
#define NH 16
#define HD 64
#define ZT (BB * NH)
#define EROWS 4224   // 4095 used + zero pad

// split-bf16 operands
__device__ __nv_bfloat16 g_qh[ZT * SS * HD], g_ql[ZT * SS * HD];
__device__ __nv_bfloat16 g_kh[ZT * SS * HD], g_kl[ZT * SS * HD];
__device__ __nv_bfloat16 g_vh[ZT * SS * HD], g_vl[ZT * SS * HD];
__device__ __nv_bfloat16 g_eh[EROWS * HD], g_el[EROWS * HD];
// split-bf16 probs (written by softmax, consumed by pv)
__device__ __nv_bfloat16 g_ph[(size_t)ZT * SS * SS];
__device__ __nv_bfloat16 g_pl[(size_t)ZT * SS * SS];

#define SW128(o) ((o) ^ (((o) >> 3) & 0x70))

__device__ __forceinline__ uint32_t smem_u32(const void* p) {
    uint32_t a;
    asm("{ .reg .u64 t; cvta.to.shared.u64 t, %1; cvt.u32.u64 %0, t; }"
        : "=r"(a) : "l"(p));
    return a;
}
__device__ __forceinline__ void ldsm4(uint32_t r[4], uint32_t addr) {
    asm volatile("ldmatrix.sync.aligned.m8n8.x4.shared.b16 {%0,%1,%2,%3}, [%4];"
        : "=r"(r[0]), "=r"(r[1]), "=r"(r[2]), "=r"(r[3]) : "r"(addr));
}
__device__ __forceinline__ void ldsm4t(uint32_t r[4], uint32_t addr) {
    asm volatile("ldmatrix.sync.aligned.m8n8.x4.trans.shared.b16 {%0,%1,%2,%3}, [%4];"
        : "=r"(r[0]), "=r"(r[1]), "=r"(r[2]), "=r"(r[3]) : "r"(addr));
}
__device__ __forceinline__ void mma_bf16(float c[4], const uint32_t a[4],
                                         const uint32_t b[2]) {
    asm volatile(
        "mma.sync.aligned.m16n8k16.row.col.f32.bf16.bf16.f32 "
        "{%0,%1,%2,%3}, {%4,%5,%6,%7}, {%8,%9}, {%0,%1,%2,%3};"
        : "+f"(c[0]), "+f"(c[1]), "+f"(c[2]), "+f"(c[3])
        : "r"(a[0]), "r"(a[1]), "r"(a[2]), "r"(a[3]), "r"(b[0]), "r"(b[1]));
}
__device__ __forceinline__ void cp16(uint32_t smem_addr, const void* gptr) {
    asm volatile("cp.async.cg.shared.global [%0], [%1], 16;"
                 :: "r"(smem_addr), "l"(gptr));
}
__device__ __forceinline__ void split8(const float4& f0, const float4& f1,
                                       uint4& h4, uint4& l4) {
    float f[8] = {f0.x, f0.y, f0.z, f0.w, f1.x, f1.y, f1.z, f1.w};
    __nv_bfloat162* hp = (__nv_bfloat162*)&h4;
    __nv_bfloat162* lp = (__nv_bfloat162*)&l4;
#pragma unroll
    for (int j = 0; j < 4; j++) {
        __nv_bfloat16 a = __float2bfloat16(f[2 * j]);
        __nv_bfloat16 b = __float2bfloat16(f[2 * j + 1]);
        __nv_bfloat16 al = __float2bfloat16(f[2 * j] - __bfloat162float(a));
        __nv_bfloat16 bl = __float2bfloat16(f[2 * j + 1] - __bfloat162float(b));
        hp[j] = __halves2bfloat162(a, b);
        lp[j] = __halves2bfloat162(al, bl);
    }
}

// ---------------------------------------------------------------------------
// Kernel 1: fused QKV projection. q,k,v all written as split-bf16 (hi/lo).
// ---------------------------------------------------------------------------
__global__ __launch_bounds__(256) void qkv_kernel(
    const float* __restrict__ A, const float* __restrict__ W,
    const float* __restrict__ bias)
{
    __shared__ float As[8][128];
    __shared__ float Ws[8][128];
    const int tid = threadIdx.x;
    const int bx = blockIdx.x, by = blockIdx.y;
    const int tx = tid % 16, ty = tid / 16;

    float acc[8][8];
#pragma unroll
    for (int i = 0; i < 8; i++)
#pragma unroll
        for (int j = 0; j < 8; j++) acc[i][j] = 0.f;

    const int ar = tid >> 1;
    const int ac = (tid & 1) * 4;
    const int wr = tid >> 5;
    const int wc = (tid & 31) * 4;

    const float* Aptr = A + (size_t)(by * 128 + ar) * HH + ac;
    const float* Wptr = W + (size_t)wr * 3072 + bx * 128 + wc;

    for (int kt = 0; kt < HH / 8; kt++) {
        float4 av = *(const float4*)(Aptr + kt * 8);
        float4 wv = *(const float4*)(Wptr + (size_t)kt * 8 * 3072);
        As[ac + 0][ar] = av.x; As[ac + 1][ar] = av.y;
        As[ac + 2][ar] = av.z; As[ac + 3][ar] = av.w;
        *(float4*)&Ws[wr][wc] = wv;
        __syncthreads();
#pragma unroll
        for (int k = 0; k < 8; k++) {
            float a[8], b[8];
#pragma unroll
            for (int i = 0; i < 8; i++) a[i] = As[k][ty * 8 + i];
#pragma unroll
            for (int j = 0; j < 8; j++) b[j] = Ws[k][tx * 8 + j];
#pragma unroll
            for (int i = 0; i < 8; i++)
#pragma unroll
                for (int j = 0; j < 8; j++) acc[i][j] += a[i] * b[j];
        }
        __syncthreads();
    }

    const int n0 = bx * 128 + tx * 8;
    const int which = n0 / 1024;
    const int h = (n0 % 1024) / 64;
    const int d0 = n0 % 64;
    float bv[8];
#pragma unroll
    for (int j = 0; j < 8; j++) bv[j] = bias[n0 + j];

    __nv_bfloat16* dh = (which == 0) ? g_qh : (which == 1) ? g_kh : g_vh;
    __nv_bfloat16* dl = (which == 0) ? g_ql : (which == 1) ? g_kl : g_vl;

#pragma unroll
    for (int i = 0; i < 8; i++) {
        int m = by * 128 + ty * 8 + i;
        int b = m / SS, s = m % SS;
        size_t off = ((size_t)(b * NH + h) * SS + s) * HD + d0;
        uint4 uh, ul;
        split8(make_float4(acc[i][0] + bv[0], acc[i][1] + bv[1],
                           acc[i][2] + bv[2], acc[i][3] + bv[3]),
               make_float4(acc[i][4] + bv[4], acc[i][5] + bv[5],
                           acc[i][6] + bv[6], acc[i][7] + bv[7]), uh, ul);
        *(uint4*)(dh + off) = uh;
        *(uint4*)(dl + off) = ul;
    }
}

// ---------------------------------------------------------------------------
// Kernel 1b: split dist_emb into bf16 hi/lo (zero-padded rows beyond 4094)
// ---------------------------------------------------------------------------
__global__ __launch_bounds__(256) void split_e_kernel(const float* __restrict__ dist_emb)
{
    int i = blockIdx.x * 256 + threadIdx.x;
    if (i >= EROWS * HD) return;
    float e = (i < 4095 * HD) ? dist_emb[i] : 0.f;
    __nv_bfloat16 h = __float2bfloat16(e);
    g_eh[i] = h;
    g_el[i] = __float2bfloat16(e - __bfloat162float(h));
}

// ---------------------------------------------------------------------------
// Kernel 2: score kernel, 20 warps (640 thr), warp tile 32m x 32n.
// Column space [S(64) | QE(128) | KE(128)] = 320 cols, 10 chunks of 32.
// warp w: m0=(w&1)*32, chunk=w>>1.
// out[u,v] = 0.125*S[u,v] + QE[u, 63+u-v] + KE[v, 63+u-v] + mask[v]
// ---------------------------------------------------------------------------
#define OFF_QH 0
#define OFF_QL 8192
#define OFF_KH 16384
#define OFF_KL 24576
#define OFF_EH 32768
#define OFF_EL 49152
// staging overlays operands after compute
#define OFF_SS 0                 // 64*66*4  = 16896
#define OFF_QES 16896            // 64*130*4 = 33280
#define OFF_KES 50176            // 64*130*4 = 33280 -> 83456
#define OFF_MASK 83456
#define SC_SMEM 83968

__global__ __launch_bounds__(640) void score_mma_kernel(
    const float* __restrict__ mask, float* __restrict__ probs)
{
    extern __shared__ char smem[];
    const uint32_t sb = smem_u32(smem);
    const int tid = threadIdx.x, wid = tid >> 5, lane = tid & 31;
    const int z = blockIdx.z;
    const int l0 = blockIdx.y * 64, r0 = blockIdx.x * 64;
    const int base2 = l0 - r0 + 1984;

    // ---- loads ----
    if (tid < 64)
        ((float*)(smem + OFF_MASK))[tid] = mask[(z / NH) * SS + r0 + tid];
    if (tid < 512) {
        int row = tid >> 3, c = tid & 7;
        uint32_t so = SW128((uint32_t)(row * 128 + c * 16));
        size_t gq = ((size_t)z * SS + l0 + row) * HD + c * 8;
        size_t gk = ((size_t)z * SS + r0 + row) * HD + c * 8;
        *(uint4*)(smem + OFF_QH + so) = *(const uint4*)(g_qh + gq);
        *(uint4*)(smem + OFF_QL + so) = *(const uint4*)(g_ql + gq);
        *(uint4*)(smem + OFF_KH + so) = *(const uint4*)(g_kh + gk);
        *(uint4*)(smem + OFF_KL + so) = *(const uint4*)(g_kl + gk);
    }
    for (int i = tid; i < 1024; i += 640) {
        int row = i >> 3, c = i & 7;
        uint32_t so = SW128((uint32_t)(row * 128 + c * 16));
        size_t ge = (size_t)(base2 + row) * HD + c * 8;
        *(uint4*)(smem + OFF_EH + so) = *(const uint4*)(g_eh + ge);
        *(uint4*)(smem + OFF_EL + so) = *(const uint4*)(g_el + ge);
    }
    __syncthreads();

    // ---- warp roles ----
    const int m0 = (wid & 1) * 32;
    const int chunk = wid >> 1;
    uint32_t aH, aL, bH, bL;
    int bn0;
    if (chunk < 6) {
        aH = sb + OFF_QH; aL = sb + OFF_QL;
        if (chunk < 2) { bH = sb + OFF_KH; bL = sb + OFF_KL; bn0 = chunk * 32; }
        else           { bH = sb + OFF_EH; bL = sb + OFF_EL; bn0 = (chunk - 2) * 32; }
    } else {
        aH = sb + OFF_KH; aL = sb + OFF_KL;
        bH = sb + OFF_EH; bL = sb + OFF_EL;
        bn0 = (chunk - 6) * 32;
    }

    float acc[2][4][4];
#pragma unroll
    for (int i = 0; i < 2; i++)
#pragma unroll
        for (int j = 0; j < 4; j++)
#pragma unroll
            for (int c = 0; c < 4; c++) acc[i][j][c] = 0.f;

    const int aRow = lane & 15;
    const int aBx = (lane >> 4) * 16;
    const int bRow = (lane & 7) + (lane >> 4) * 8;
    const int bBx = ((lane >> 3) & 1) * 16;

#pragma unroll
    for (int ks = 0; ks < 4; ks++) {
        const int kb = ks * 32;
        uint32_t AH[2][4], AL[2][4], BH[2][4], BL[2][4];
#pragma unroll
        for (int mf = 0; mf < 2; mf++) {
            uint32_t off = SW128((uint32_t)((m0 + mf * 16 + aRow) * 128 + kb + aBx));
            ldsm4(AH[mf], aH + off);
            ldsm4(AL[mf], aL + off);
        }
#pragma unroll
        for (int nt = 0; nt < 2; nt++) {
            uint32_t off = SW128((uint32_t)((bn0 + nt * 16 + bRow) * 128 + kb + bBx));
            ldsm4(BH[nt], bH + off);
            ldsm4(BL[nt], bL + off);
        }
#pragma unroll
        for (int mf = 0; mf < 2; mf++)
#pragma unroll
            for (int nf = 0; nf < 4; nf++) {
                const uint32_t* bh = &BH[nf >> 1][(nf & 1) * 2];
                const uint32_t* bl = &BL[nf >> 1][(nf & 1) * 2];
                mma_bf16(acc[mf][nf], AH[mf], bh);
                mma_bf16(acc[mf][nf], AH[mf], bl);
                mma_bf16(acc[mf][nf], AL[mf], bh);
            }
    }
    __syncthreads();

    // ---- stage accumulators ----
    {
        float* sp; int stride, cbase;
        if (chunk < 2)      { sp = (float*)(smem + OFF_SS);  stride = 66;  cbase = chunk * 32; }
        else if (chunk < 6) { sp = (float*)(smem + OFF_QES); stride = 130; cbase = (chunk - 2) * 32; }
        else                { sp = (float*)(smem + OFF_KES); stride = 130; cbase = (chunk - 6) * 32; }
        const int r = lane >> 2, c2 = 2 * (lane & 3);
#pragma unroll
        for (int mf = 0; mf < 2; mf++) {
            int u = m0 + mf * 16 + r;
#pragma unroll
            for (int nf = 0; nf < 4; nf++) {
                int cc = cbase + nf * 8 + c2;
                *(float2*)&sp[u * stride + cc] =
                    make_float2(acc[mf][nf][0], acc[mf][nf][1]);
                *(float2*)&sp[(u + 8) * stride + cc] =
                    make_float2(acc[mf][nf][2], acc[mf][nf][3]);
            }
        }
    }
    __syncthreads();

    // ---- gather + write ----
    if (tid < 512) {
        const float* Ss  = (const float*)(smem + OFF_SS);
        const float* QEs = (const float*)(smem + OFF_QES);
        const float* KEs = (const float*)(smem + OFF_KES);
        const float* msk = (const float*)(smem + OFF_MASK);
        const int u = tid >> 3;
        const int v0 = (tid & 7) * 8;
        float* orow = probs + ((size_t)z * SS + l0 + u) * SS + r0;
#pragma unroll
        for (int g = 0; g < 2; g++) {
            float4 o;
            float* po = (float*)&o;
#pragma unroll
            for (int c = 0; c < 4; c++) {
                int v = v0 + g * 4 + c;
                int j = u - v + 63;
                po[c] = 0.125f * Ss[u * 66 + v] + QEs[u * 130 + j]
                      + KEs[v * 130 + j] + msk[v];
            }
            *(float4*)(orow + v0 + g * 4) = o;
        }
    }
}

// ---------------------------------------------------------------------------
// Kernel 3: in-place row softmax over 2048; also emits split-bf16 probs.
// ---------------------------------------------------------------------------
__global__ __launch_bounds__(256) void softmax_kernel(float* __restrict__ probs)
{
    __shared__ float red[256];
    const int tid = threadIdx.x;
    const size_t rowb = (size_t)blockIdx.x * SS;
    float4* p = (float4*)(probs + rowb);

    float4 x0 = p[tid];
    float4 x1 = p[tid + 256];

    float m = fmaxf(fmaxf(fmaxf(x0.x, x0.y), fmaxf(x0.z, x0.w)),
                    fmaxf(fmaxf(x1.x, x1.y), fmaxf(x1.z, x1.w)));
    red[tid] = m;
    __syncthreads();
#pragma unroll
    for (int s = 128; s > 0; s >>= 1) {
        if (tid < s) red[tid] = fmaxf(red[tid], red[tid + s]);
        __syncthreads();
    }
    m = red[0];
    __syncthreads();

    x0.x = __expf(x0.x - m); x0.y = __expf(x0.y - m);
    x0.z = __expf(x0.z - m); x0.w = __expf(x0.w - m);
    x1.x = __expf(x1.x - m); x1.y = __expf(x1.y - m);
    x1.z = __expf(x1.z - m); x1.w = __expf(x1.w - m);

    float sum = (x0.x + x0.y) + (x0.z + x0.w) + (x1.x + x1.y) + (x1.z + x1.w);
    red[tid] = sum;
    __syncthreads();
#pragma unroll
    for (int s = 128; s > 0; s >>= 1) {
        if (tid < s) red[tid] += red[tid + s];
        __syncthreads();
    }
    float inv = 1.f / red[0];

    x0.x *= inv; x0.y *= inv; x0.z *= inv; x0.w *= inv;
    x1.x *= inv; x1.y *= inv; x1.z *= inv; x1.w *= inv;
    p[tid] = x0;
    p[tid + 256] = x1;

    // split-bf16 copies for the PV kernel
    const float4 xs[2] = {x0, x1};
#pragma unroll
    for (int g = 0; g < 2; g++) {
        const float* f = (const float*)&xs[g];
        uint2 uh, ul;
        __nv_bfloat162* hp = (__nv_bfloat162*)&uh;
        __nv_bfloat162* lp = (__nv_bfloat162*)&ul;
#pragma unroll
        for (int j = 0; j < 2; j++) {
            __nv_bfloat16 a = __float2bfloat16(f[2 * j]);
            __nv_bfloat16 b = __float2bfloat16(f[2 * j + 1]);
            __nv_bfloat16 al = __float2bfloat16(f[2 * j] - __bfloat162float(a));
            __nv_bfloat16 bl = __float2bfloat16(f[2 * j + 1] - __bfloat162float(b));
            hp[j] = __halves2bfloat162(a, b);
            lp[j] = __halves2bfloat162(al, bl);
        }
        size_t off = rowb + g * 1024 + tid * 4;
        *(uint2*)(g_ph + off) = uh;
        *(uint2*)(g_pl + off) = ul;
    }
}

// ---------------------------------------------------------------------------
// Kernel 4: ctx = P @ V, split-bf16 inputs, cp.async double-buffered.
// Block: (z, 128 l). 8 warps, warp tile 32m x 32d. k-chunks of 64.
// Stage: PH 16K | PL 16K | VH 8K | VL 8K = 48K, x2 stages.
// ---------------------------------------------------------------------------
#define PVS_PH 0
#define PVS_PL 16384
#define PVS_VH 32768
#define PVS_VL 40960
#define PVS_STRIDE 49152
#define PV_SMEM (2 * PVS_STRIDE)

__global__ __launch_bounds__(256) void pv_mma_kernel(float* __restrict__ ctx)
{
    extern __shared__ char smem[];
    const uint32_t sb = smem_u32(smem);
    const int tid = threadIdx.x, wid = tid >> 5, lane = tid & 31;
    const int z = blockIdx.y;
    const int l0 = blockIdx.x * 128;
    const int m0 = (wid >> 1) * 32, d0 = (wid & 1) * 32;

    const size_t pbase = ((size_t)z * SS + l0) * SS;
    const size_t vbase = (size_t)z * SS * HD;

    // fill stage s with k-chunk rt
    auto fill = [&](int s, int rt) {
        const uint32_t stg = sb + s * PVS_STRIDE;
#pragma unroll
        for (int j = 0; j < 4; j++) {
            int idx = tid + 256 * j;
            int row = idx >> 3, c = idx & 7;
            uint32_t so = SW128((uint32_t)(row * 128 + c * 16));
            size_t g = pbase + (size_t)row * SS + rt * 64 + c * 8;
            cp16(stg + PVS_PH + so, g_ph + g);
            cp16(stg + PVS_PL + so, g_pl + g);
        }
#pragma unroll
        for (int j = 0; j < 2; j++) {
            int idx = tid + 256 * j;
            int row = idx >> 3, c = idx & 7;
            uint32_t so = SW128((uint32_t)(row * 128 + c * 16));
            size_t g = vbase + (size_t)(rt * 64 + row) * HD + c * 8;
            cp16(stg + PVS_VH + so, g_vh + g);
            cp16(stg + PVS_VL + so, g_vl + g);
        }
        asm volatile("cp.async.commit_group;" ::: "memory");
    };

    float acc[2][4][4];
#pragma unroll
    for (int i = 0; i < 2; i++)
#pragma unroll
        for (int j = 0; j < 4; j++)
#pragma unroll
            for (int c = 0; c < 4; c++) acc[i][j][c] = 0.f;

    const int aRow = lane & 15;
    const int aBx = (lane >> 4) * 16;

    fill(0, 0);
    fill(1, 1);

    for (int rt = 0; rt < 32; rt++) {
        if (rt < 31) asm volatile("cp.async.wait_group 1;" ::: "memory");
        else         asm volatile("cp.async.wait_group 0;" ::: "memory");
        __syncthreads();

        const uint32_t stg = sb + (rt & 1) * PVS_STRIDE;
#pragma unroll
        for (int ks = 0; ks < 4; ks++) {
            const int kb = ks * 32;
            uint32_t AH[2][4], AL[2][4], BH[2][4], BL[2][4];
#pragma unroll
            for (int mf = 0; mf < 2; mf++) {
                uint32_t off = SW128((uint32_t)((m0 + mf * 16 + aRow) * 128 + kb + aBx));
                ldsm4(AH[mf], stg + PVS_PH + off);
                ldsm4(AL[mf], stg + PVS_PL + off);
            }
#pragma unroll
            for (int nt = 0; nt < 2; nt++) {
                uint32_t off = SW128((uint32_t)((ks * 16 + aRow) * 128
                                                + (d0 + nt * 16) * 2 + aBx));
                ldsm4t(BH[nt], stg + PVS_VH + off);
                ldsm4t(BL[nt], stg + PVS_VL + off);
            }
#pragma unroll
            for (int mf = 0; mf < 2; mf++)
#pragma unroll
                for (int nf = 0; nf < 4; nf++) {
                    const uint32_t* bh = &BH[nf >> 1][(nf & 1) * 2];
                    const uint32_t* bl = &BL[nf >> 1][(nf & 1) * 2];
                    mma_bf16(acc[mf][nf], AH[mf], bh);
                    mma_bf16(acc[mf][nf], AH[mf], bl);
                    mma_bf16(acc[mf][nf], AL[mf], bh);
                }
        }
        __syncthreads();
        if (rt + 2 < 32) fill(rt & 1, rt + 2);
    }

    // write ctx
    const int b = z / NH, h = z % NH;
    const int r = lane >> 2, c2 = 2 * (lane & 3);
#pragma unroll
    for (int mf = 0; mf < 2; mf++) {
        int l = l0 + m0 + mf * 16 + r;
#pragma unroll
        for (int nf = 0; nf < 4; nf++) {
            int d = d0 + nf * 8 + c2;
            float* o = ctx + ((size_t)b * SS + l) * HH + h * HD + d;
            *(float2*)o = make_float2(acc[mf][nf][0], acc[mf][nf][1]);
            *(float2*)(o + (size_t)8 * HH) = make_float2(acc[mf][nf][2], acc[mf][nf][3]);
        }
    }
}

// ---------------------------------------------------------------------------
extern "C" void kernel_launch(void* const* d_in, const int* in_sizes, int n_in,
                              void* d_out, int out_size)
{
    const float* hidden   = (const float*)d_in[0];
    const float* mask     = (const float*)d_in[1];
    const float* qkv_w    = (const float*)d_in[2];
    const float* qkv_b    = (const float*)d_in[3];
    const float* dist_emb = (const float*)d_in[4];

    float* out = (float*)d_out;
    float* ctx = out;
    float* probs = out + (size_t)BB * SS * HH;

    // 1) QKV projection -> split-bf16 q,k,v
    qkv_kernel<<<dim3(3072 / 128, 4096 / 128), 256>>>(hidden, qkv_w, qkv_b);

    // 1b) split dist_emb into bf16 hi/lo
    split_e_kernel<<<(EROWS * HD + 255) / 256, 256>>>(dist_emb);

    // 2) warp-MMA scores (+ bias + mask) -> probs buffer (raw)
    cudaFuncSetAttribute(score_mma_kernel,
                         cudaFuncAttributeMaxDynamicSharedMemorySize, SC_SMEM);
    score_mma_kernel<<<dim3(SS / 64, SS / 64, ZT), 640, SC_SMEM>>>(mask, probs);

    // 3) softmax in place (+ split-bf16 copy)
    softmax_kernel<<<ZT * SS, 256>>>(probs);

    // 4) ctx = probs @ v (cp.async double-buffered MMA)
    cudaFuncSetAttribute(pv_mma_kernel,
                         cudaFuncAttributeMaxDynamicSharedMemorySize, PV_SMEM);
    pv_mma_kernel<<<dim3(SS / 128, ZT), 256, PV_SMEM>>>(ctx);
}

// round 7
// speedup vs baseline: 1.6235x; 1.4457x over previous
#include <cuda_runtime.h>
#include <cuda_fp16.h>
#include <cstdint>

#define BB 2
#define SS 2048
#define HH 1024
#define NH 16
#define HD 64
#define ZT (BB * NH)
#define EROWS 4096   // 4095 used + 1 zero pad row

// single-fp16 operands
__device__ __half g_qh[ZT * SS * HD], g_kh[ZT * SS * HD], g_vh[ZT * SS * HD];
__device__ __half g_eh[EROWS * HD];
__device__ __half g_ph[(size_t)ZT * SS * SS];   // fp16 probs (softmax -> pv)

#define SW128(o) ((o) ^ (((o) >> 3) & 0x70))

__device__ __forceinline__ uint32_t smem_u32(const void* p) {
    uint32_t a;
    asm("{ .reg .u64 t; cvta.to.shared.u64 t, %1; cvt.u32.u64 %0, t; }"
        : "=r"(a) : "l"(p));
    return a;
}
__device__ __forceinline__ void ldsm4(uint32_t r[4], uint32_t addr) {
    asm volatile("ldmatrix.sync.aligned.m8n8.x4.shared.b16 {%0,%1,%2,%3}, [%4];"
        : "=r"(r[0]), "=r"(r[1]), "=r"(r[2]), "=r"(r[3]) : "r"(addr));
}
__device__ __forceinline__ void ldsm4t(uint32_t r[4], uint32_t addr) {
    asm volatile("ldmatrix.sync.aligned.m8n8.x4.trans.shared.b16 {%0,%1,%2,%3}, [%4];"
        : "=r"(r[0]), "=r"(r[1]), "=r"(r[2]), "=r"(r[3]) : "r"(addr));
}
__device__ __forceinline__ void mma_f16(float c[4], const uint32_t a[4],
                                        const uint32_t b[2]) {
    asm volatile(
        "mma.sync.aligned.m16n8k16.row.col.f32.f16.f16.f32 "
        "{%0,%1,%2,%3}, {%4,%5,%6,%7}, {%8,%9}, {%0,%1,%2,%3};"
        : "+f"(c[0]), "+f"(c[1]), "+f"(c[2]), "+f"(c[3])
        : "r"(a[0]), "r"(a[1]), "r"(a[2]), "r"(a[3]), "r"(b[0]), "r"(b[1]));
}
__device__ __forceinline__ void cp16(uint32_t smem_addr, const void* gptr) {
    asm volatile("cp.async.cg.shared.global [%0], [%1], 16;"
                 :: "r"(smem_addr), "l"(gptr));
}

// ---------------------------------------------------------------------------
// Kernel 1: fused QKV projection -> fp16 q,k,v in [z][s][d] layout.
// ---------------------------------------------------------------------------
__global__ __launch_bounds__(256) void qkv_kernel(
    const float* __restrict__ A, const float* __restrict__ W,
    const float* __restrict__ bias)
{
    __shared__ float As[8][128];
    __shared__ float Ws[8][128];
    const int tid = threadIdx.x;
    const int bx = blockIdx.x, by = blockIdx.y;
    const int tx = tid % 16, ty = tid / 16;

    float acc[8][8];
#pragma unroll
    for (int i = 0; i < 8; i++)
#pragma unroll
        for (int j = 0; j < 8; j++) acc[i][j] = 0.f;

    const int ar = tid >> 1;
    const int ac = (tid & 1) * 4;
    const int wr = tid >> 5;
    const int wc = (tid & 31) * 4;

    const float* Aptr = A + (size_t)(by * 128 + ar) * HH + ac;
    const float* Wptr = W + (size_t)wr * 3072 + bx * 128 + wc;

    for (int kt = 0; kt < HH / 8; kt++) {
        float4 av = *(const float4*)(Aptr + kt * 8);
        float4 wv = *(const float4*)(Wptr + (size_t)kt * 8 * 3072);
        As[ac + 0][ar] = av.x; As[ac + 1][ar] = av.y;
        As[ac + 2][ar] = av.z; As[ac + 3][ar] = av.w;
        *(float4*)&Ws[wr][wc] = wv;
        __syncthreads();
#pragma unroll
        for (int k = 0; k < 8; k++) {
            float a[8], b[8];
#pragma unroll
            for (int i = 0; i < 8; i++) a[i] = As[k][ty * 8 + i];
#pragma unroll
            for (int j = 0; j < 8; j++) b[j] = Ws[k][tx * 8 + j];
#pragma unroll
            for (int i = 0; i < 8; i++)
#pragma unroll
                for (int j = 0; j < 8; j++) acc[i][j] += a[i] * b[j];
        }
        __syncthreads();
    }

    const int n0 = bx * 128 + tx * 8;
    const int which = n0 / 1024;
    const int h = (n0 % 1024) / 64;
    const int d0 = n0 % 64;
    float bv[8];
#pragma unroll
    for (int j = 0; j < 8; j++) bv[j] = bias[n0 + j];

    __half* dst = (which == 0) ? g_qh : (which == 1) ? g_kh : g_vh;

#pragma unroll
    for (int i = 0; i < 8; i++) {
        int m = by * 128 + ty * 8 + i;
        int b = m / SS, s = m % SS;
        size_t off = ((size_t)(b * NH + h) * SS + s) * HD + d0;
        uint4 u;
        __half2* hp = (__half2*)&u;
#pragma unroll
        for (int j = 0; j < 4; j++)
            hp[j] = __floats2half2_rn(acc[i][2 * j] + bv[2 * j],
                                      acc[i][2 * j + 1] + bv[2 * j + 1]);
        *(uint4*)(dst + off) = u;
    }
}

// ---------------------------------------------------------------------------
// Kernel 1b: dist_emb -> fp16 (row 4095 zero-padded)
// ---------------------------------------------------------------------------
__global__ __launch_bounds__(256) void split_e_kernel(const float* __restrict__ dist_emb)
{
    int i = blockIdx.x * 256 + threadIdx.x;
    if (i >= EROWS * HD) return;
    float e = (i < 4095 * HD) ? dist_emb[i] : 0.f;
    g_eh[i] = __float2half_rn(e);
}

// ---------------------------------------------------------------------------
// Kernel 2: persistent score kernel. Block = (l-tile, z); loops 32 r-tiles
// with cp.async double-buffered K and E. 20 warps, warp tile 32m x 32n.
// Column space [S(64) | QE(128) | KE(128)], chunk = wid>>1 (0..9), m0=(wid&1)*32.
// out[u,v] = 0.125*S[u,v] + QE[u,63+u-v] + KE[v,63+u-v] + mask[r]
// ---------------------------------------------------------------------------
#define SCO_QH 0                      // 8192
#define SCO_KH 8192                   // 2 x 8192 -> 24576
#define SCO_EH 24576                  // 2 x 16384 -> 57344
#define SCO_SS 57344                  // 64*66*4 = 16896 -> 74240
#define SCO_QES 74240                 // 64*130*4 = 33280 -> 107520
#define SCO_KES 107520                // 33280 -> 140800
#define SCO_MASK 140800               // 2048 floats -> 148992
#define SC_SMEM 148992

__global__ __launch_bounds__(640) void score_mma_kernel(
    const float* __restrict__ mask, float* __restrict__ probs)
{
    extern __shared__ char smem[];
    const uint32_t sb = smem_u32(smem);
    const int tid = threadIdx.x, wid = tid >> 5, lane = tid & 31;
    const int l0 = blockIdx.x * 64;
    const int z = blockIdx.y;

    // ---- prologue: mask row + Q tile (once per block) ----
    if (tid < 512) {
        ((float4*)(smem + SCO_MASK))[tid] =
            ((const float4*)(mask + (size_t)(z / NH) * SS))[tid];
        int row = tid >> 3, c = tid & 7;
        uint32_t so = SW128((uint32_t)(row * 128 + c * 16));
        *(uint4*)(smem + SCO_QH + so) =
            *(const uint4*)(g_qh + ((size_t)z * SS + l0 + row) * HD + c * 8);
    }

    // cp.async fill of K/E for r-tile rt into buffer s
    auto fill = [&](int s, int rt) {
        const uint32_t kbuf = sb + SCO_KH + s * 8192;
        const uint32_t ebuf = sb + SCO_EH + s * 16384;
        const int base2 = l0 - rt * 64 + 1984;
        for (int i = tid; i < 1536; i += 640) {
            if (i < 512) {
                int row = i >> 3, c = i & 7;
                cp16(kbuf + SW128((uint32_t)(row * 128 + c * 16)),
                     g_kh + ((size_t)z * SS + rt * 64 + row) * HD + c * 8);
            } else {
                int j = i - 512;
                int row = j >> 3, c = j & 7;
                cp16(ebuf + SW128((uint32_t)(row * 128 + c * 16)),
                     g_eh + (size_t)(base2 + row) * HD + c * 8);
            }
        }
        asm volatile("cp.async.commit_group;" ::: "memory");
    };

    fill(0, 0);
    fill(1, 1);

    // ---- warp roles ----
    const int m0 = (wid & 1) * 32;
    const int chunk = wid >> 1;     // 0-1:S  2-5:QE  6-9:KE
    const int bn0 = (chunk < 2) ? chunk * 32
                  : (chunk < 6) ? (chunk - 2) * 32 : (chunk - 6) * 32;

    const int aRow = lane & 15;
    const int aBx = (lane >> 4) * 16;
    const int bRow = (lane & 7) + (lane >> 4) * 8;
    const int bBx = ((lane >> 3) & 1) * 16;

    for (int r0 = 0; r0 < 32; r0++) {
        if (r0 < 31) asm volatile("cp.async.wait_group 1;" ::: "memory");
        else         asm volatile("cp.async.wait_group 0;" ::: "memory");
        __syncthreads();

        const int cur = r0 & 1;
        const uint32_t kbuf = sb + SCO_KH + cur * 8192;
        const uint32_t ebuf = sb + SCO_EH + cur * 16384;
        const uint32_t aBase = (chunk < 6) ? (sb + SCO_QH) : kbuf;
        const uint32_t bBase = (chunk < 2) ? kbuf : ebuf;

        float acc[2][4][4];
#pragma unroll
        for (int i = 0; i < 2; i++)
#pragma unroll
            for (int j = 0; j < 4; j++)
#pragma unroll
                for (int c = 0; c < 4; c++) acc[i][j][c] = 0.f;

#pragma unroll
        for (int ks = 0; ks < 4; ks++) {
            const int kb = ks * 32;
            uint32_t Af[2][4], Bf[2][4];
#pragma unroll
            for (int mf = 0; mf < 2; mf++)
                ldsm4(Af[mf], aBase + SW128((uint32_t)((m0 + mf * 16 + aRow) * 128 + kb + aBx)));
#pragma unroll
            for (int nt = 0; nt < 2; nt++)
                ldsm4(Bf[nt], bBase + SW128((uint32_t)((bn0 + nt * 16 + bRow) * 128 + kb + bBx)));
#pragma unroll
            for (int mf = 0; mf < 2; mf++)
#pragma unroll
                for (int nf = 0; nf < 4; nf++)
                    mma_f16(acc[mf][nf], Af[mf], &Bf[nf >> 1][(nf & 1) * 2]);
        }

        // ---- stage accumulators ----
        {
            float* sp; int stride;
            if (chunk < 2)      { sp = (float*)(smem + SCO_SS);  stride = 66;  }
            else if (chunk < 6) { sp = (float*)(smem + SCO_QES); stride = 130; }
            else                { sp = (float*)(smem + SCO_KES); stride = 130; }
            const int r = lane >> 2, c2 = 2 * (lane & 3);
#pragma unroll
            for (int mf = 0; mf < 2; mf++) {
                int u = m0 + mf * 16 + r;
#pragma unroll
                for (int nf = 0; nf < 4; nf++) {
                    int cc = bn0 + nf * 8 + c2;
                    *(float2*)&sp[u * stride + cc] =
                        make_float2(acc[mf][nf][0], acc[mf][nf][1]);
                    *(float2*)&sp[(u + 8) * stride + cc] =
                        make_float2(acc[mf][nf][2], acc[mf][nf][3]);
                }
            }
        }
        __syncthreads();

        // prefetch next-next tile (overlaps with gather/write)
        if (r0 + 2 < 32) fill(cur, r0 + 2);

        // ---- gather + write ----
        if (tid < 512) {
            const float* Ss  = (const float*)(smem + SCO_SS);
            const float* QEs = (const float*)(smem + SCO_QES);
            const float* KEs = (const float*)(smem + SCO_KES);
            const float* msk = (const float*)(smem + SCO_MASK);
            const int u = tid >> 3;
            const int v0 = (tid & 7) * 8;
            float* orow = probs + ((size_t)z * SS + l0 + u) * SS + r0 * 64;
#pragma unroll
            for (int g = 0; g < 2; g++) {
                float4 o;
                float* po = (float*)&o;
#pragma unroll
                for (int c = 0; c < 4; c++) {
                    int v = v0 + g * 4 + c;
                    int j = u - v + 63;
                    po[c] = 0.125f * Ss[u * 66 + v] + QEs[u * 130 + j]
                          + KEs[v * 130 + j] + msk[r0 * 64 + v];
                }
                *(float4*)(orow + v0 + g * 4) = o;
            }
        }
        // top-of-loop sync separates gather reads from next stage writes
    }
}

// ---------------------------------------------------------------------------
// Kernel 3: in-place row softmax; also emits fp16 probs for pv.
// ---------------------------------------------------------------------------
__global__ __launch_bounds__(256) void softmax_kernel(float* __restrict__ probs)
{
    __shared__ float red[256];
    const int tid = threadIdx.x;
    const size_t rowb = (size_t)blockIdx.x * SS;
    float4* p = (float4*)(probs + rowb);

    float4 x0 = p[tid];
    float4 x1 = p[tid + 256];

    float m = fmaxf(fmaxf(fmaxf(x0.x, x0.y), fmaxf(x0.z, x0.w)),
                    fmaxf(fmaxf(x1.x, x1.y), fmaxf(x1.z, x1.w)));
    red[tid] = m;
    __syncthreads();
#pragma unroll
    for (int s = 128; s > 0; s >>= 1) {
        if (tid < s) red[tid] = fmaxf(red[tid], red[tid + s]);
        __syncthreads();
    }
    m = red[0];
    __syncthreads();

    x0.x = __expf(x0.x - m); x0.y = __expf(x0.y - m);
    x0.z = __expf(x0.z - m); x0.w = __expf(x0.w - m);
    x1.x = __expf(x1.x - m); x1.y = __expf(x1.y - m);
    x1.z = __expf(x1.z - m); x1.w = __expf(x1.w - m);

    float sum = (x0.x + x0.y) + (x0.z + x0.w) + (x1.x + x1.y) + (x1.z + x1.w);
    red[tid] = sum;
    __syncthreads();
#pragma unroll
    for (int s = 128; s > 0; s >>= 1) {
        if (tid < s) red[tid] += red[tid + s];
        __syncthreads();
    }
    float inv = 1.f / red[0];

    x0.x *= inv; x0.y *= inv; x0.z *= inv; x0.w *= inv;
    x1.x *= inv; x1.y *= inv; x1.z *= inv; x1.w *= inv;
    p[tid] = x0;
    p[tid + 256] = x1;

    // fp16 copy for pv
    uint4 u;
    __half2* hp = (__half2*)&u;
    hp[0] = __floats2half2_rn(x0.x, x0.y);
    hp[1] = __floats2half2_rn(x0.z, x0.w);
    hp[2] = __floats2half2_rn(x1.x, x1.y);
    hp[3] = __floats2half2_rn(x1.z, x1.w);
    // x0 -> cols tid*4.., x1 -> cols 1024 + tid*4..
    *(uint2*)(g_ph + rowb + tid * 4) = make_uint2(u.x, u.y);
    *(uint2*)(g_ph + rowb + 1024 + tid * 4) = make_uint2(u.z, u.w);
}

// ---------------------------------------------------------------------------
// Kernel 4: ctx = P @ V, single fp16 term, cp.async double-buffered.
// Block (z, 128 l), 8 warps, warp tile 32m x 32d, k-chunks of 64.
// Stage: PH 16K | VH 8K = 24K, x2.
// ---------------------------------------------------------------------------
#define PVS_PH 0
#define PVS_VH 16384
#define PVS_STRIDE 24576
#define PV_SMEM (2 * PVS_STRIDE)

__global__ __launch_bounds__(256) void pv_mma_kernel(float* __restrict__ ctx)
{
    extern __shared__ char smem[];
    const uint32_t sb = smem_u32(smem);
    const int tid = threadIdx.x, wid = tid >> 5, lane = tid & 31;
    const int z = blockIdx.y;
    const int l0 = blockIdx.x * 128;
    const int m0 = (wid >> 1) * 32, d0 = (wid & 1) * 32;

    const size_t pbase = ((size_t)z * SS + l0) * SS;
    const size_t vbase = (size_t)z * SS * HD;

    auto fill = [&](int s, int rt) {
        const uint32_t stg = sb + s * PVS_STRIDE;
#pragma unroll
        for (int j = 0; j < 4; j++) {
            int idx = tid + 256 * j;
            int row = idx >> 3, c = idx & 7;
            uint32_t so = SW128((uint32_t)(row * 128 + c * 16));
            cp16(stg + PVS_PH + so, g_ph + pbase + (size_t)row * SS + rt * 64 + c * 8);
        }
#pragma unroll
        for (int j = 0; j < 2; j++) {
            int idx = tid + 256 * j;
            int row = idx >> 3, c = idx & 7;
            uint32_t so = SW128((uint32_t)(row * 128 + c * 16));
            cp16(stg + PVS_VH + so, g_vh + vbase + (size_t)(rt * 64 + row) * HD + c * 8);
        }
        asm volatile("cp.async.commit_group;" ::: "memory");
    };

    float acc[2][4][4];
#pragma unroll
    for (int i = 0; i < 2; i++)
#pragma unroll
        for (int j = 0; j < 4; j++)
#pragma unroll
            for (int c = 0; c < 4; c++) acc[i][j][c] = 0.f;

    const int aRow = lane & 15;
    const int aBx = (lane >> 4) * 16;

    fill(0, 0);
    fill(1, 1);

    for (int rt = 0; rt < 32; rt++) {
        if (rt < 31) asm volatile("cp.async.wait_group 1;" ::: "memory");
        else         asm volatile("cp.async.wait_group 0;" ::: "memory");
        __syncthreads();

        const uint32_t stg = sb + (rt & 1) * PVS_STRIDE;
#pragma unroll
        for (int ks = 0; ks < 4; ks++) {
            const int kb = ks * 32;
            uint32_t Af[2][4], Bf[2][4];
#pragma unroll
            for (int mf = 0; mf < 2; mf++)
                ldsm4(Af[mf], stg + PVS_PH +
                      SW128((uint32_t)((m0 + mf * 16 + aRow) * 128 + kb + aBx)));
#pragma unroll
            for (int nt = 0; nt < 2; nt++)
                ldsm4t(Bf[nt], stg + PVS_VH +
                       SW128((uint32_t)((ks * 16 + aRow) * 128 + (d0 + nt * 16) * 2 + aBx)));
#pragma unroll
            for (int mf = 0; mf < 2; mf++)
#pragma unroll
                for (int nf = 0; nf < 4; nf++)
                    mma_f16(acc[mf][nf], Af[mf], &Bf[nf >> 1][(nf & 1) * 2]);
        }
        __syncthreads();
        if (rt + 2 < 32) fill(rt & 1, rt + 2);
    }

    const int b = z / NH, h = z % NH;
    const int r = lane >> 2, c2 = 2 * (lane & 3);
#pragma unroll
    for (int mf = 0; mf < 2; mf++) {
        int l = l0 + m0 + mf * 16 + r;
#pragma unroll
        for (int nf = 0; nf < 4; nf++) {
            int d = d0 + nf * 8 + c2;
            float* o = ctx + ((size_t)b * SS + l) * HH + h * HD + d;
            *(float2*)o = make_float2(acc[mf][nf][0], acc[mf][nf][1]);
            *(float2*)(o + (size_t)8 * HH) = make_float2(acc[mf][nf][2], acc[mf][nf][3]);
        }
    }
}

// ---------------------------------------------------------------------------
extern "C" void kernel_launch(void* const* d_in, const int* in_sizes, int n_in,
                              void* d_out, int out_size)
{
    const float* hidden   = (const float*)d_in[0];
    const float* mask     = (const float*)d_in[1];
    const float* qkv_w    = (const float*)d_in[2];
    const float* qkv_b    = (const float*)d_in[3];
    const float* dist_emb = (const float*)d_in[4];

    float* out = (float*)d_out;
    float* ctx = out;
    float* probs = out + (size_t)BB * SS * HH;

    // 1) QKV projection -> fp16 q,k,v
    qkv_kernel<<<dim3(3072 / 128, 4096 / 128), 256>>>(hidden, qkv_w, qkv_b);

    // 1b) dist_emb -> fp16
    split_e_kernel<<<(EROWS * HD + 255) / 256, 256>>>(dist_emb);

    // 2) persistent warp-MMA scores (+ bias + mask) -> probs buffer (raw)
    cudaFuncSetAttribute(score_mma_kernel,
                         cudaFuncAttributeMaxDynamicSharedMemorySize, SC_SMEM);
    score_mma_kernel<<<dim3(SS / 64, ZT), 640, SC_SMEM>>>(mask, probs);

    // 3) softmax in place (+ fp16 copy)
    softmax_kernel<<<ZT * SS, 256>>>(probs);

    // 4) ctx = probs @ v
    cudaFuncSetAttribute(pv_mma_kernel,
                         cudaFuncAttributeMaxDynamicSharedMemorySize, PV_SMEM);
    pv_mma_kernel<<<dim3(SS / 128, ZT), 256, PV_SMEM>>>(ctx);
}

// round 8
// speedup vs baseline: 2.4721x; 1.5227x over previous
#include <cuda_runtime.h>
#include <cuda_fp16.h>
#include <cstdint>

#define BB 2
#define SS 2048
#define HH 1024
#define NH 16
#define HD 64
#define ZT (BB * NH)
#define EROWS 4096   // 4095 used + 1 zero pad row

// fp16 operands
__device__ __half g_qh[ZT * SS * HD], g_kh[ZT * SS * HD], g_vh[ZT * SS * HD];
__device__ __half g_eh[EROWS * HD];
__device__ __half g_ph[(size_t)ZT * SS * SS];   // fp16 probs (softmax -> pv)
// fp16 copies of GEMM inputs
__device__ __half g_h16[BB * SS * HH];          // hidden  [4096][1024]
__device__ __half g_w16[HH * 3 * HH];           // qkv_w   [1024][3072]

#define SW128(o) ((o) ^ (((o) >> 3) & 0x70))

__device__ __forceinline__ uint32_t smem_u32(const void* p) {
    uint32_t a;
    asm("{ .reg .u64 t; cvta.to.shared.u64 t, %1; cvt.u32.u64 %0, t; }"
        : "=r"(a) : "l"(p));
    return a;
}
__device__ __forceinline__ void ldsm4(uint32_t r[4], uint32_t addr) {
    asm volatile("ldmatrix.sync.aligned.m8n8.x4.shared.b16 {%0,%1,%2,%3}, [%4];"
        : "=r"(r[0]), "=r"(r[1]), "=r"(r[2]), "=r"(r[3]) : "r"(addr));
}
__device__ __forceinline__ void ldsm4t(uint32_t r[4], uint32_t addr) {
    asm volatile("ldmatrix.sync.aligned.m8n8.x4.trans.shared.b16 {%0,%1,%2,%3}, [%4];"
        : "=r"(r[0]), "=r"(r[1]), "=r"(r[2]), "=r"(r[3]) : "r"(addr));
}
__device__ __forceinline__ void mma_f16(float c[4], const uint32_t a[4],
                                        const uint32_t b[2]) {
    asm volatile(
        "mma.sync.aligned.m16n8k16.row.col.f32.f16.f16.f32 "
        "{%0,%1,%2,%3}, {%4,%5,%6,%7}, {%8,%9}, {%0,%1,%2,%3};"
        : "+f"(c[0]), "+f"(c[1]), "+f"(c[2]), "+f"(c[3])
        : "r"(a[0]), "r"(a[1]), "r"(a[2]), "r"(a[3]), "r"(b[0]), "r"(b[1]));
}
__device__ __forceinline__ void cp16(uint32_t smem_addr, const void* gptr) {
    asm volatile("cp.async.cg.shared.global [%0], [%1], 16;"
                 :: "r"(smem_addr), "l"(gptr));
}

// ---------------------------------------------------------------------------
// Convert kernels: fp32 -> fp16 (vectorized, 4 elems/thread)
// ---------------------------------------------------------------------------
__global__ __launch_bounds__(256) void conv_h_kernel(const float* __restrict__ src)
{
    int i = blockIdx.x * 256 + threadIdx.x;
    float4 v = ((const float4*)src)[i];
    ((__half2*)g_h16)[2 * i] = __floats2half2_rn(v.x, v.y);
    ((__half2*)g_h16)[2 * i + 1] = __floats2half2_rn(v.z, v.w);
}
__global__ __launch_bounds__(256) void conv_w_kernel(const float* __restrict__ src)
{
    int i = blockIdx.x * 256 + threadIdx.x;
    float4 v = ((const float4*)src)[i];
    ((__half2*)g_w16)[2 * i] = __floats2half2_rn(v.x, v.y);
    ((__half2*)g_w16)[2 * i + 1] = __floats2half2_rn(v.z, v.w);
}

// ---------------------------------------------------------------------------
// Kernel 1: QKV projection on HMMA.  C[4096,3072] = H[4096,1024] @ W[1024,3072]
// Block tile 128m x 128n, 8 warps (32m x 64n each), k-chunks of 64,
// cp.async double-buffered. Epilogue: +bias, fp16, scatter to g_qh/g_kh/g_vh.
// ---------------------------------------------------------------------------
#define QKO_A 0        // 2 x 16K
#define QKO_W 32768    // 2 x 16K (each stage: two 8K subtiles of 64 cols)
#define QK_SMEM 65536

__global__ __launch_bounds__(256, 2) void qkv_mma_kernel(
    const float* __restrict__ bias)
{
    extern __shared__ char smem[];
    const uint32_t sb = smem_u32(smem);
    const int tid = threadIdx.x, wid = tid >> 5, lane = tid & 31;
    const int bx = blockIdx.x, by = blockIdx.y;
    const int m0 = (wid >> 1) * 32;
    const int wx = wid & 1;              // n half: 0 or 1 (64 cols each)

    auto fill = [&](int s, int kt) {
        const uint32_t stgA = sb + QKO_A + s * 16384;
        const uint32_t stgW = sb + QKO_W + s * 16384;
#pragma unroll
        for (int j = 0; j < 4; j++) {
            int idx = tid + 256 * j;
            int row = idx >> 3, c = idx & 7;      // A: 128 rows x 8 chunks
            cp16(stgA + SW128((uint32_t)(row * 128 + c * 16)),
                 g_h16 + (size_t)(by * 128 + row) * HH + kt * 64 + c * 8);
        }
#pragma unroll
        for (int j = 0; j < 4; j++) {
            int idx = tid + 256 * j;
            int row = idx >> 4, c = idx & 15;     // W: 64 rows x 16 chunks
            cp16(stgW + (c >> 3) * 8192 + SW128((uint32_t)(row * 128 + (c & 7) * 16)),
                 g_w16 + (size_t)(kt * 64 + row) * 3072 + bx * 128 + c * 8);
        }
        asm volatile("cp.async.commit_group;" ::: "memory");
    };

    float acc[2][8][4];
#pragma unroll
    for (int i = 0; i < 2; i++)
#pragma unroll
        for (int j = 0; j < 8; j++)
#pragma unroll
            for (int c = 0; c < 4; c++) acc[i][j][c] = 0.f;

    const int aRow = lane & 15;
    const int aBx = (lane >> 4) * 16;

    fill(0, 0);
    fill(1, 1);

    for (int kt = 0; kt < 16; kt++) {
        if (kt < 15) asm volatile("cp.async.wait_group 1;" ::: "memory");
        else         asm volatile("cp.async.wait_group 0;" ::: "memory");
        __syncthreads();

        const uint32_t stgA = sb + QKO_A + (kt & 1) * 16384;
        const uint32_t wsub = sb + QKO_W + (kt & 1) * 16384 + wx * 8192;
#pragma unroll
        for (int ks = 0; ks < 4; ks++) {
            uint32_t Af[2][4], Bf[4][4];
#pragma unroll
            for (int mf = 0; mf < 2; mf++)
                ldsm4(Af[mf], stgA +
                      SW128((uint32_t)((m0 + mf * 16 + aRow) * 128 + ks * 32 + aBx)));
#pragma unroll
            for (int nt = 0; nt < 4; nt++)
                ldsm4t(Bf[nt], wsub +
                       SW128((uint32_t)((ks * 16 + aRow) * 128 + nt * 32 + aBx)));
#pragma unroll
            for (int mf = 0; mf < 2; mf++)
#pragma unroll
                for (int nf = 0; nf < 8; nf++)
                    mma_f16(acc[mf][nf], Af[mf], &Bf[nf >> 1][(nf & 1) * 2]);
        }
        __syncthreads();
        if (kt + 2 < 16) fill(kt & 1, kt + 2);
    }

    // epilogue: +bias, convert fp16, scatter
    const int r = lane >> 2, c2 = 2 * (lane & 3);
#pragma unroll
    for (int nf = 0; nf < 8; nf++) {
        int n = bx * 128 + wx * 64 + nf * 8 + c2;
        float b0 = bias[n], b1 = bias[n + 1];
        int which = n >> 10;
        int h = (n & 1023) >> 6;
        int d = n & 63;
        __half* dst = (which == 0) ? g_qh : (which == 1) ? g_kh : g_vh;
#pragma unroll
        for (int mf = 0; mf < 2; mf++) {
            int m = by * 128 + m0 + mf * 16 + r;
            int b = m >> 11, s = m & 2047;
            size_t off = ((size_t)(b * NH + h) * SS + s) * HD + d;
            *(__half2*)(dst + off) =
                __floats2half2_rn(acc[mf][nf][0] + b0, acc[mf][nf][1] + b1);
            *(__half2*)(dst + off + (size_t)8 * HD) =
                __floats2half2_rn(acc[mf][nf][2] + b0, acc[mf][nf][3] + b1);
        }
    }
}

// ---------------------------------------------------------------------------
// Kernel 1b: dist_emb -> fp16 (row 4095 zero-padded)
// ---------------------------------------------------------------------------
__global__ __launch_bounds__(256) void split_e_kernel(const float* __restrict__ dist_emb)
{
    int i = blockIdx.x * 256 + threadIdx.x;
    if (i >= EROWS * HD) return;
    float e = (i < 4095 * HD) ? dist_emb[i] : 0.f;
    g_eh[i] = __float2half_rn(e);
}

// ---------------------------------------------------------------------------
// Kernel 2: persistent score kernel (unchanged from R7).
// ---------------------------------------------------------------------------
#define SCO_QH 0
#define SCO_KH 8192
#define SCO_EH 24576
#define SCO_SS 57344
#define SCO_QES 74240
#define SCO_KES 107520
#define SCO_MASK 140800
#define SC_SMEM 148992

__global__ __launch_bounds__(640) void score_mma_kernel(
    const float* __restrict__ mask, float* __restrict__ probs)
{
    extern __shared__ char smem[];
    const uint32_t sb = smem_u32(smem);
    const int tid = threadIdx.x, wid = tid >> 5, lane = tid & 31;
    const int l0 = blockIdx.x * 64;
    const int z = blockIdx.y;

    if (tid < 512) {
        ((float4*)(smem + SCO_MASK))[tid] =
            ((const float4*)(mask + (size_t)(z / NH) * SS))[tid];
        int row = tid >> 3, c = tid & 7;
        uint32_t so = SW128((uint32_t)(row * 128 + c * 16));
        *(uint4*)(smem + SCO_QH + so) =
            *(const uint4*)(g_qh + ((size_t)z * SS + l0 + row) * HD + c * 8);
    }

    auto fill = [&](int s, int rt) {
        const uint32_t kbuf = sb + SCO_KH + s * 8192;
        const uint32_t ebuf = sb + SCO_EH + s * 16384;
        const int base2 = l0 - rt * 64 + 1984;
        for (int i = tid; i < 1536; i += 640) {
            if (i < 512) {
                int row = i >> 3, c = i & 7;
                cp16(kbuf + SW128((uint32_t)(row * 128 + c * 16)),
                     g_kh + ((size_t)z * SS + rt * 64 + row) * HD + c * 8);
            } else {
                int j = i - 512;
                int row = j >> 3, c = j & 7;
                cp16(ebuf + SW128((uint32_t)(row * 128 + c * 16)),
                     g_eh + (size_t)(base2 + row) * HD + c * 8);
            }
        }
        asm volatile("cp.async.commit_group;" ::: "memory");
    };

    fill(0, 0);
    fill(1, 1);

    const int m0 = (wid & 1) * 32;
    const int chunk = wid >> 1;
    const int bn0 = (chunk < 2) ? chunk * 32
                  : (chunk < 6) ? (chunk - 2) * 32 : (chunk - 6) * 32;

    const int aRow = lane & 15;
    const int aBx = (lane >> 4) * 16;
    const int bRow = (lane & 7) + (lane >> 4) * 8;
    const int bBx = ((lane >> 3) & 1) * 16;

    for (int r0 = 0; r0 < 32; r0++) {
        if (r0 < 31) asm volatile("cp.async.wait_group 1;" ::: "memory");
        else         asm volatile("cp.async.wait_group 0;" ::: "memory");
        __syncthreads();

        const int cur = r0 & 1;
        const uint32_t kbuf = sb + SCO_KH + cur * 8192;
        const uint32_t ebuf = sb + SCO_EH + cur * 16384;
        const uint32_t aBase = (chunk < 6) ? (sb + SCO_QH) : kbuf;
        const uint32_t bBase = (chunk < 2) ? kbuf : ebuf;

        float acc[2][4][4];
#pragma unroll
        for (int i = 0; i < 2; i++)
#pragma unroll
            for (int j = 0; j < 4; j++)
#pragma unroll
                for (int c = 0; c < 4; c++) acc[i][j][c] = 0.f;

#pragma unroll
        for (int ks = 0; ks < 4; ks++) {
            const int kb = ks * 32;
            uint32_t Af[2][4], Bf[2][4];
#pragma unroll
            for (int mf = 0; mf < 2; mf++)
                ldsm4(Af[mf], aBase + SW128((uint32_t)((m0 + mf * 16 + aRow) * 128 + kb + aBx)));
#pragma unroll
            for (int nt = 0; nt < 2; nt++)
                ldsm4(Bf[nt], bBase + SW128((uint32_t)((bn0 + nt * 16 + bRow) * 128 + kb + bBx)));
#pragma unroll
            for (int mf = 0; mf < 2; mf++)
#pragma unroll
                for (int nf = 0; nf < 4; nf++)
                    mma_f16(acc[mf][nf], Af[mf], &Bf[nf >> 1][(nf & 1) * 2]);
        }

        {
            float* sp; int stride;
            if (chunk < 2)      { sp = (float*)(smem + SCO_SS);  stride = 66;  }
            else if (chunk < 6) { sp = (float*)(smem + SCO_QES); stride = 130; }
            else                { sp = (float*)(smem + SCO_KES); stride = 130; }
            const int r = lane >> 2, c2 = 2 * (lane & 3);
#pragma unroll
            for (int mf = 0; mf < 2; mf++) {
                int u = m0 + mf * 16 + r;
#pragma unroll
                for (int nf = 0; nf < 4; nf++) {
                    int cc = bn0 + nf * 8 + c2;
                    *(float2*)&sp[u * stride + cc] =
                        make_float2(acc[mf][nf][0], acc[mf][nf][1]);
                    *(float2*)&sp[(u + 8) * stride + cc] =
                        make_float2(acc[mf][nf][2], acc[mf][nf][3]);
                }
            }
        }
        __syncthreads();

        if (r0 + 2 < 32) fill(cur, r0 + 2);

        if (tid < 512) {
            const float* Ss  = (const float*)(smem + SCO_SS);
            const float* QEs = (const float*)(smem + SCO_QES);
            const float* KEs = (const float*)(smem + SCO_KES);
            const float* msk = (const float*)(smem + SCO_MASK);
            const int u = tid >> 3;
            const int v0 = (tid & 7) * 8;
            float* orow = probs + ((size_t)z * SS + l0 + u) * SS + r0 * 64;
#pragma unroll
            for (int g = 0; g < 2; g++) {
                float4 o;
                float* po = (float*)&o;
#pragma unroll
                for (int c = 0; c < 4; c++) {
                    int v = v0 + g * 4 + c;
                    int j = u - v + 63;
                    po[c] = 0.125f * Ss[u * 66 + v] + QEs[u * 130 + j]
                          + KEs[v * 130 + j] + msk[r0 * 64 + v];
                }
                *(float4*)(orow + v0 + g * 4) = o;
            }
        }
    }
}

// ---------------------------------------------------------------------------
// Kernel 3: in-place row softmax; also emits fp16 probs for pv. (unchanged)
// ---------------------------------------------------------------------------
__global__ __launch_bounds__(256) void softmax_kernel(float* __restrict__ probs)
{
    __shared__ float red[256];
    const int tid = threadIdx.x;
    const size_t rowb = (size_t)blockIdx.x * SS;
    float4* p = (float4*)(probs + rowb);

    float4 x0 = p[tid];
    float4 x1 = p[tid + 256];

    float m = fmaxf(fmaxf(fmaxf(x0.x, x0.y), fmaxf(x0.z, x0.w)),
                    fmaxf(fmaxf(x1.x, x1.y), fmaxf(x1.z, x1.w)));
    red[tid] = m;
    __syncthreads();
#pragma unroll
    for (int s = 128; s > 0; s >>= 1) {
        if (tid < s) red[tid] = fmaxf(red[tid], red[tid + s]);
        __syncthreads();
    }
    m = red[0];
    __syncthreads();

    x0.x = __expf(x0.x - m); x0.y = __expf(x0.y - m);
    x0.z = __expf(x0.z - m); x0.w = __expf(x0.w - m);
    x1.x = __expf(x1.x - m); x1.y = __expf(x1.y - m);
    x1.z = __expf(x1.z - m); x1.w = __expf(x1.w - m);

    float sum = (x0.x + x0.y) + (x0.z + x0.w) + (x1.x + x1.y) + (x1.z + x1.w);
    red[tid] = sum;
    __syncthreads();
#pragma unroll
    for (int s = 128; s > 0; s >>= 1) {
        if (tid < s) red[tid] += red[tid + s];
        __syncthreads();
    }
    float inv = 1.f / red[0];

    x0.x *= inv; x0.y *= inv; x0.z *= inv; x0.w *= inv;
    x1.x *= inv; x1.y *= inv; x1.z *= inv; x1.w *= inv;
    p[tid] = x0;
    p[tid + 256] = x1;

    uint4 u;
    __half2* hp = (__half2*)&u;
    hp[0] = __floats2half2_rn(x0.x, x0.y);
    hp[1] = __floats2half2_rn(x0.z, x0.w);
    hp[2] = __floats2half2_rn(x1.x, x1.y);
    hp[3] = __floats2half2_rn(x1.z, x1.w);
    *(uint2*)(g_ph + rowb + tid * 4) = make_uint2(u.x, u.y);
    *(uint2*)(g_ph + rowb + 1024 + tid * 4) = make_uint2(u.z, u.w);
}

// ---------------------------------------------------------------------------
// Kernel 4: ctx = P @ V (unchanged from R7).
// ---------------------------------------------------------------------------
#define PVS_PH 0
#define PVS_VH 16384
#define PVS_STRIDE 24576
#define PV_SMEM (2 * PVS_STRIDE)

__global__ __launch_bounds__(256) void pv_mma_kernel(float* __restrict__ ctx)
{
    extern __shared__ char smem[];
    const uint32_t sb = smem_u32(smem);
    const int tid = threadIdx.x, wid = tid >> 5, lane = tid & 31;
    const int z = blockIdx.y;
    const int l0 = blockIdx.x * 128;
    const int m0 = (wid >> 1) * 32, d0 = (wid & 1) * 32;

    const size_t pbase = ((size_t)z * SS + l0) * SS;
    const size_t vbase = (size_t)z * SS * HD;

    auto fill = [&](int s, int rt) {
        const uint32_t stg = sb + s * PVS_STRIDE;
#pragma unroll
        for (int j = 0; j < 4; j++) {
            int idx = tid + 256 * j;
            int row = idx >> 3, c = idx & 7;
            uint32_t so = SW128((uint32_t)(row * 128 + c * 16));
            cp16(stg + PVS_PH + so, g_ph + pbase + (size_t)row * SS + rt * 64 + c * 8);
        }
#pragma unroll
        for (int j = 0; j < 2; j++) {
            int idx = tid + 256 * j;
            int row = idx >> 3, c = idx & 7;
            uint32_t so = SW128((uint32_t)(row * 128 + c * 16));
            cp16(stg + PVS_VH + so, g_vh + vbase + (size_t)(rt * 64 + row) * HD + c * 8);
        }
        asm volatile("cp.async.commit_group;" ::: "memory");
    };

    float acc[2][4][4];
#pragma unroll
    for (int i = 0; i < 2; i++)
#pragma unroll
        for (int j = 0; j < 4; j++)
#pragma unroll
            for (int c = 0; c < 4; c++) acc[i][j][c] = 0.f;

    const int aRow = lane & 15;
    const int aBx = (lane >> 4) * 16;

    fill(0, 0);
    fill(1, 1);

    for (int rt = 0; rt < 32; rt++) {
        if (rt < 31) asm volatile("cp.async.wait_group 1;" ::: "memory");
        else         asm volatile("cp.async.wait_group 0;" ::: "memory");
        __syncthreads();

        const uint32_t stg = sb + (rt & 1) * PVS_STRIDE;
#pragma unroll
        for (int ks = 0; ks < 4; ks++) {
            const int kb = ks * 32;
            uint32_t Af[2][4], Bf[2][4];
#pragma unroll
            for (int mf = 0; mf < 2; mf++)
                ldsm4(Af[mf], stg + PVS_PH +
                      SW128((uint32_t)((m0 + mf * 16 + aRow) * 128 + kb + aBx)));
#pragma unroll
            for (int nt = 0; nt < 2; nt++)
                ldsm4t(Bf[nt], stg + PVS_VH +
                       SW128((uint32_t)((ks * 16 + aRow) * 128 + (d0 + nt * 16) * 2 + aBx)));
#pragma unroll
            for (int mf = 0; mf < 2; mf++)
#pragma unroll
                for (int nf = 0; nf < 4; nf++)
                    mma_f16(acc[mf][nf], Af[mf], &Bf[nf >> 1][(nf & 1) * 2]);
        }
        __syncthreads();
        if (rt + 2 < 32) fill(rt & 1, rt + 2);
    }

    const int b = z / NH, h = z % NH;
    const int r = lane >> 2, c2 = 2 * (lane & 3);
#pragma unroll
    for (int mf = 0; mf < 2; mf++) {
        int l = l0 + m0 + mf * 16 + r;
#pragma unroll
        for (int nf = 0; nf < 4; nf++) {
            int d = d0 + nf * 8 + c2;
            float* o = ctx + ((size_t)b * SS + l) * HH + h * HD + d;
            *(float2*)o = make_float2(acc[mf][nf][0], acc[mf][nf][1]);
            *(float2*)(o + (size_t)8 * HH) = make_float2(acc[mf][nf][2], acc[mf][nf][3]);
        }
    }
}

// ---------------------------------------------------------------------------
extern "C" void kernel_launch(void* const* d_in, const int* in_sizes, int n_in,
                              void* d_out, int out_size)
{
    const float* hidden   = (const float*)d_in[0];
    const float* mask     = (const float*)d_in[1];
    const float* qkv_w    = (const float*)d_in[2];
    const float* qkv_b    = (const float*)d_in[3];
    const float* dist_emb = (const float*)d_in[4];

    float* out = (float*)d_out;
    float* ctx = out;
    float* probs = out + (size_t)BB * SS * HH;

    // 1) fp16 conversions of GEMM inputs + E table
    conv_h_kernel<<<BB * SS * HH / 1024, 256>>>(hidden);
    conv_w_kernel<<<HH * 3 * HH / 1024, 256>>>(qkv_w);
    split_e_kernel<<<(EROWS * HD + 255) / 256, 256>>>(dist_emb);

    // 2) QKV projection on HMMA -> g_qh/g_kh/g_vh
    cudaFuncSetAttribute(qkv_mma_kernel,
                         cudaFuncAttributeMaxDynamicSharedMemorySize, QK_SMEM);
    qkv_mma_kernel<<<dim3(3072 / 128, 4096 / 128), 256, QK_SMEM>>>(qkv_b);

    // 3) persistent warp-MMA scores (+ bias + mask) -> probs buffer (raw)
    cudaFuncSetAttribute(score_mma_kernel,
                         cudaFuncAttributeMaxDynamicSharedMemorySize, SC_SMEM);
    score_mma_kernel<<<dim3(SS / 64, ZT), 640, SC_SMEM>>>(mask, probs);

    // 4) softmax in place (+ fp16 copy)
    softmax_kernel<<<ZT * SS, 256>>>(probs);

    // 5) ctx = probs @ v
    cudaFuncSetAttribute(pv_mma_kernel,
                         cudaFuncAttributeMaxDynamicSharedMemorySize, PV_SMEM);
    pv_mma_kernel<<<dim3(SS / 128, ZT), 256, PV_SMEM>>>(ctx);
}

// round 11
// speedup vs baseline: 2.4818x; 1.0039x over previous
#include <cuda_runtime.h>
#include <cuda_fp16.h>
#include <cstdint>

#define BB 2
#define SS 2048
#define HH 1024
#define NH 16
#define HD 64
#define ZT (BB * NH)
#define EROWS 4096   // 4095 used + 1 zero pad row

// fp16 operands
__device__ __half g_qh[ZT * SS * HD], g_kh[ZT * SS * HD], g_vh[ZT * SS * HD];
__device__ __half g_eh[EROWS * HD];
__device__ __half g_ph[(size_t)ZT * SS * SS];   // fp16 probs (normalize -> pv)
// fp16 copies of GEMM inputs
__device__ __half g_h16[BB * SS * HH];          // hidden  [4096][1024]
__device__ __half g_w16[HH * 3 * HH];           // qkv_w   [1024][3072]
// per-row softmax stats: (max, 1/sum)
__device__ float2 g_rowstat[ZT * SS];

#define SW128(o) ((o) ^ (((o) >> 3) & 0x70))

__device__ __forceinline__ uint32_t smem_u32(const void* p) {
    uint32_t a;
    asm("{ .reg .u64 t; cvta.to.shared.u64 t, %1; cvt.u32.u64 %0, t; }"
        : "=r"(a) : "l"(p));
    return a;
}
__device__ __forceinline__ void ldsm4(uint32_t r[4], uint32_t addr) {
    asm volatile("ldmatrix.sync.aligned.m8n8.x4.shared.b16 {%0,%1,%2,%3}, [%4];"
        : "=r"(r[0]), "=r"(r[1]), "=r"(r[2]), "=r"(r[3]) : "r"(addr));
}
__device__ __forceinline__ void ldsm4t(uint32_t r[4], uint32_t addr) {
    asm volatile("ldmatrix.sync.aligned.m8n8.x4.trans.shared.b16 {%0,%1,%2,%3}, [%4];"
        : "=r"(r[0]), "=r"(r[1]), "=r"(r[2]), "=r"(r[3]) : "r"(addr));
}
__device__ __forceinline__ void mma_f16(float c[4], const uint32_t a[4],
                                        const uint32_t b[2]) {
    asm volatile(
        "mma.sync.aligned.m16n8k16.row.col.f32.f16.f16.f32 "
        "{%0,%1,%2,%3}, {%4,%5,%6,%7}, {%8,%9}, {%0,%1,%2,%3};"
        : "+f"(c[0]), "+f"(c[1]), "+f"(c[2]), "+f"(c[3])
        : "r"(a[0]), "r"(a[1]), "r"(a[2]), "r"(a[3]), "r"(b[0]), "r"(b[1]));
}
__device__ __forceinline__ void cp16(uint32_t smem_addr, const void* gptr) {
    asm volatile("cp.async.cg.shared.global [%0], [%1], 16;"
                 :: "r"(smem_addr), "l"(gptr));
}

// ---------------------------------------------------------------------------
// Convert kernels: fp32 -> fp16 (vectorized, 4 elems/thread)
// ---------------------------------------------------------------------------
__global__ __launch_bounds__(256) void conv_h_kernel(const float* __restrict__ src)
{
    int i = blockIdx.x * 256 + threadIdx.x;
    float4 v = ((const float4*)src)[i];
    ((__half2*)g_h16)[2 * i] = __floats2half2_rn(v.x, v.y);
    ((__half2*)g_h16)[2 * i + 1] = __floats2half2_rn(v.z, v.w);
}
__global__ __launch_bounds__(256) void conv_w_kernel(const float* __restrict__ src)
{
    int i = blockIdx.x * 256 + threadIdx.x;
    float4 v = ((const float4*)src)[i];
    ((__half2*)g_w16)[2 * i] = __floats2half2_rn(v.x, v.y);
    ((__half2*)g_w16)[2 * i + 1] = __floats2half2_rn(v.z, v.w);
}

// ---------------------------------------------------------------------------
// Kernel 1: QKV projection on HMMA (unchanged from R8, verified 78.8us).
// ---------------------------------------------------------------------------
#define QKO_A 0
#define QKO_W 32768
#define QK_SMEM 65536

__global__ __launch_bounds__(256, 2) void qkv_mma_kernel(
    const float* __restrict__ bias)
{
    extern __shared__ char smem[];
    const uint32_t sb = smem_u32(smem);
    const int tid = threadIdx.x, wid = tid >> 5, lane = tid & 31;
    const int bx = blockIdx.x, by = blockIdx.y;
    const int m0 = (wid >> 1) * 32;
    const int wx = wid & 1;

    auto fill = [&](int s, int kt) {
        const uint32_t stgA = sb + QKO_A + s * 16384;
        const uint32_t stgW = sb + QKO_W + s * 16384;
#pragma unroll
        for (int j = 0; j < 4; j++) {
            int idx = tid + 256 * j;
            int row = idx >> 3, c = idx & 7;
            cp16(stgA + SW128((uint32_t)(row * 128 + c * 16)),
                 g_h16 + (size_t)(by * 128 + row) * HH + kt * 64 + c * 8);
        }
#pragma unroll
        for (int j = 0; j < 4; j++) {
            int idx = tid + 256 * j;
            int row = idx >> 4, c = idx & 15;
            cp16(stgW + (c >> 3) * 8192 + SW128((uint32_t)(row * 128 + (c & 7) * 16)),
                 g_w16 + (size_t)(kt * 64 + row) * 3072 + bx * 128 + c * 8);
        }
        asm volatile("cp.async.commit_group;" ::: "memory");
    };

    float acc[2][8][4];
#pragma unroll
    for (int i = 0; i < 2; i++)
#pragma unroll
        for (int j = 0; j < 8; j++)
#pragma unroll
            for (int c = 0; c < 4; c++) acc[i][j][c] = 0.f;

    const int aRow = lane & 15;
    const int aBx = (lane >> 4) * 16;

    fill(0, 0);
    fill(1, 1);

    for (int kt = 0; kt < 16; kt++) {
        if (kt < 15) asm volatile("cp.async.wait_group 1;" ::: "memory");
        else         asm volatile("cp.async.wait_group 0;" ::: "memory");
        __syncthreads();

        const uint32_t stgA = sb + QKO_A + (kt & 1) * 16384;
        const uint32_t wsub = sb + QKO_W + (kt & 1) * 16384 + wx * 8192;
#pragma unroll
        for (int ks = 0; ks < 4; ks++) {
            uint32_t Af[2][4], Bf[4][4];
#pragma unroll
            for (int mf = 0; mf < 2; mf++)
                ldsm4(Af[mf], stgA +
                      SW128((uint32_t)((m0 + mf * 16 + aRow) * 128 + ks * 32 + aBx)));
#pragma unroll
            for (int nt = 0; nt < 4; nt++)
                ldsm4t(Bf[nt], wsub +
                       SW128((uint32_t)((ks * 16 + aRow) * 128 + nt * 32 + aBx)));
#pragma unroll
            for (int mf = 0; mf < 2; mf++)
#pragma unroll
                for (int nf = 0; nf < 8; nf++)
                    mma_f16(acc[mf][nf], Af[mf], &Bf[nf >> 1][(nf & 1) * 2]);
        }
        __syncthreads();
        if (kt + 2 < 16) fill(kt & 1, kt + 2);
    }

    const int r = lane >> 2, c2 = 2 * (lane & 3);
#pragma unroll
    for (int nf = 0; nf < 8; nf++) {
        int n = bx * 128 + wx * 64 + nf * 8 + c2;
        float b0 = bias[n], b1 = bias[n + 1];
        int which = n >> 10;
        int h = (n & 1023) >> 6;
        int d = n & 63;
        __half* dst = (which == 0) ? g_qh : (which == 1) ? g_kh : g_vh;
#pragma unroll
        for (int mf = 0; mf < 2; mf++) {
            int m = by * 128 + m0 + mf * 16 + r;
            int b = m >> 11, s = m & 2047;
            size_t off = ((size_t)(b * NH + h) * SS + s) * HD + d;
            *(__half2*)(dst + off) =
                __floats2half2_rn(acc[mf][nf][0] + b0, acc[mf][nf][1] + b1);
            *(__half2*)(dst + off + (size_t)8 * HD) =
                __floats2half2_rn(acc[mf][nf][2] + b0, acc[mf][nf][3] + b1);
        }
    }
}

// ---------------------------------------------------------------------------
// Kernel 1b: dist_emb -> fp16 (row 4095 zero-padded)
// ---------------------------------------------------------------------------
__global__ __launch_bounds__(256) void split_e_kernel(const float* __restrict__ dist_emb)
{
    int i = blockIdx.x * 256 + threadIdx.x;
    if (i >= EROWS * HD) return;
    float e = (i < 4095 * HD) ? dist_emb[i] : 0.f;
    g_eh[i] = __float2half_rn(e);
}

// ---------------------------------------------------------------------------
// Kernel 2: persistent score kernel (R8 structure) + online row stats.
// Gather threads track online (max, expsum) for their (u, v0) strip; after
// the r-loop an 8-lane shfl combine yields per-row (max, 1/sum), written to
// g_rowstat. Raw scores still go to the probs buffer; normalization happens
// in a separate single-pass kernel.
// ---------------------------------------------------------------------------
#define SCO_QH 0
#define SCO_KH 8192
#define SCO_EH 24576
#define SCO_SS 57344
#define SCO_QES 74240
#define SCO_KES 107520
#define SCO_MASK 140800
#define SC_SMEM 148992

__global__ __launch_bounds__(640) void score_mma_kernel(
    const float* __restrict__ mask, float* __restrict__ probs)
{
    extern __shared__ char smem[];
    const uint32_t sb = smem_u32(smem);
    const int tid = threadIdx.x, wid = tid >> 5, lane = tid & 31;
    const int l0 = blockIdx.x * 64;
    const int z = blockIdx.y;

    if (tid < 512) {
        ((float4*)(smem + SCO_MASK))[tid] =
            ((const float4*)(mask + (size_t)(z / NH) * SS))[tid];
        int row = tid >> 3, c = tid & 7;
        uint32_t so = SW128((uint32_t)(row * 128 + c * 16));
        *(uint4*)(smem + SCO_QH + so) =
            *(const uint4*)(g_qh + ((size_t)z * SS + l0 + row) * HD + c * 8);
    }

    auto fill = [&](int s, int rt) {
        const uint32_t kbuf = sb + SCO_KH + s * 8192;
        const uint32_t ebuf = sb + SCO_EH + s * 16384;
        const int base2 = l0 - rt * 64 + 1984;
        for (int i = tid; i < 1536; i += 640) {
            if (i < 512) {
                int row = i >> 3, c = i & 7;
                cp16(kbuf + SW128((uint32_t)(row * 128 + c * 16)),
                     g_kh + ((size_t)z * SS + rt * 64 + row) * HD + c * 8);
            } else {
                int j = i - 512;
                int row = j >> 3, c = j & 7;
                cp16(ebuf + SW128((uint32_t)(row * 128 + c * 16)),
                     g_eh + (size_t)(base2 + row) * HD + c * 8);
            }
        }
        asm volatile("cp.async.commit_group;" ::: "memory");
    };

    fill(0, 0);
    fill(1, 1);

    const int m0 = (wid & 1) * 32;
    const int chunk = wid >> 1;
    const int bn0 = (chunk < 2) ? chunk * 32
                  : (chunk < 6) ? (chunk - 2) * 32 : (chunk - 6) * 32;

    const int aRow = lane & 15;
    const int aBx = (lane >> 4) * 16;
    const int bRow = (lane & 7) + (lane >> 4) * 8;
    const int bBx = ((lane >> 3) & 1) * 16;

    // online softmax state (gather threads only)
    float om = -1e30f, os = 0.f;

    for (int r0 = 0; r0 < 32; r0++) {
        if (r0 < 31) asm volatile("cp.async.wait_group 1;" ::: "memory");
        else         asm volatile("cp.async.wait_group 0;" ::: "memory");
        __syncthreads();

        const int cur = r0 & 1;
        const uint32_t kbuf = sb + SCO_KH + cur * 8192;
        const uint32_t ebuf = sb + SCO_EH + cur * 16384;
        const uint32_t aBase = (chunk < 6) ? (sb + SCO_QH) : kbuf;
        const uint32_t bBase = (chunk < 2) ? kbuf : ebuf;

        float acc[2][4][4];
#pragma unroll
        for (int i = 0; i < 2; i++)
#pragma unroll
            for (int j = 0; j < 4; j++)
#pragma unroll
                for (int c = 0; c < 4; c++) acc[i][j][c] = 0.f;

#pragma unroll
        for (int ks = 0; ks < 4; ks++) {
            const int kb = ks * 32;
            uint32_t Af[2][4], Bf[2][4];
#pragma unroll
            for (int mf = 0; mf < 2; mf++)
                ldsm4(Af[mf], aBase + SW128((uint32_t)((m0 + mf * 16 + aRow) * 128 + kb + aBx)));
#pragma unroll
            for (int nt = 0; nt < 2; nt++)
                ldsm4(Bf[nt], bBase + SW128((uint32_t)((bn0 + nt * 16 + bRow) * 128 + kb + bBx)));
#pragma unroll
            for (int mf = 0; mf < 2; mf++)
#pragma unroll
                for (int nf = 0; nf < 4; nf++)
                    mma_f16(acc[mf][nf], Af[mf], &Bf[nf >> 1][(nf & 1) * 2]);
        }

        {
            float* sp; int stride;
            if (chunk < 2)      { sp = (float*)(smem + SCO_SS);  stride = 66;  }
            else if (chunk < 6) { sp = (float*)(smem + SCO_QES); stride = 130; }
            else                { sp = (float*)(smem + SCO_KES); stride = 130; }
            const int r = lane >> 2, c2 = 2 * (lane & 3);
#pragma unroll
            for (int mf = 0; mf < 2; mf++) {
                int u = m0 + mf * 16 + r;
#pragma unroll
                for (int nf = 0; nf < 4; nf++) {
                    int cc = bn0 + nf * 8 + c2;
                    *(float2*)&sp[u * stride + cc] =
                        make_float2(acc[mf][nf][0], acc[mf][nf][1]);
                    *(float2*)&sp[(u + 8) * stride + cc] =
                        make_float2(acc[mf][nf][2], acc[mf][nf][3]);
                }
            }
        }
        __syncthreads();

        if (r0 + 2 < 32) fill(cur, r0 + 2);

        if (tid < 512) {
            const float* Ss  = (const float*)(smem + SCO_SS);
            const float* QEs = (const float*)(smem + SCO_QES);
            const float* KEs = (const float*)(smem + SCO_KES);
            const float* msk = (const float*)(smem + SCO_MASK);
            const int u = tid >> 3;
            const int v0 = (tid & 7) * 8;
            float* orow = probs + ((size_t)z * SS + l0 + u) * SS + r0 * 64;

            float4 o[2];
#pragma unroll
            for (int g = 0; g < 2; g++) {
                float* po = (float*)&o[g];
#pragma unroll
                for (int c = 0; c < 4; c++) {
                    int v = v0 + g * 4 + c;
                    int j = u - v + 63;
                    po[c] = 0.125f * Ss[u * 66 + v] + QEs[u * 130 + j]
                          + KEs[v * 130 + j] + msk[r0 * 64 + v];
                }
            }
            // online (max, expsum) update over the 8 new values
            float tm = fmaxf(fmaxf(fmaxf(o[0].x, o[0].y), fmaxf(o[0].z, o[0].w)),
                             fmaxf(fmaxf(o[1].x, o[1].y), fmaxf(o[1].z, o[1].w)));
            float mn = fmaxf(om, tm);
            float add = __expf(o[0].x - mn) + __expf(o[0].y - mn)
                      + __expf(o[0].z - mn) + __expf(o[0].w - mn)
                      + __expf(o[1].x - mn) + __expf(o[1].y - mn)
                      + __expf(o[1].z - mn) + __expf(o[1].w - mn);
            os = os * __expf(om - mn) + add;
            om = mn;

            *(float4*)(orow + v0) = o[0];
            *(float4*)(orow + v0 + 4) = o[1];
        }
    }

    // ---- combine stats per row and store (no global re-read) ----
    if (tid < 512) {
#pragma unroll
        for (int d = 4; d > 0; d >>= 1) {
            float m2 = __shfl_xor_sync(0xFFFFFFFF, om, d);
            float s2 = __shfl_xor_sync(0xFFFFFFFF, os, d);
            float mn = fmaxf(om, m2);
            os = os * __expf(om - mn) + s2 * __expf(m2 - mn);
            om = mn;
        }
        if ((tid & 7) == 0)
            g_rowstat[(size_t)z * SS + l0 + (tid >> 3)] = make_float2(om, 1.f / os);
    }
}

// ---------------------------------------------------------------------------
// Kernel 3: single-pass normalize (replaces softmax reductions). One block
// per row: read (max, 1/sum) from g_rowstat, exp+scale, write fp32 + fp16.
// ---------------------------------------------------------------------------
__global__ __launch_bounds__(256) void normalize_kernel(float* __restrict__ probs)
{
    const int tid = threadIdx.x;
    const size_t row = blockIdx.x;
    const size_t rowb = row * SS;
    const float2 st = g_rowstat[row];
    const float m = st.x, inv = st.y;

    float4* p = (float4*)(probs + rowb);
    float4 x0 = p[tid];
    float4 x1 = p[tid + 256];

    x0.x = __expf(x0.x - m) * inv; x0.y = __expf(x0.y - m) * inv;
    x0.z = __expf(x0.z - m) * inv; x0.w = __expf(x0.w - m) * inv;
    x1.x = __expf(x1.x - m) * inv; x1.y = __expf(x1.y - m) * inv;
    x1.z = __expf(x1.z - m) * inv; x1.w = __expf(x1.w - m) * inv;

    p[tid] = x0;
    p[tid + 256] = x1;

    uint4 u;
    __half2* hp = (__half2*)&u;
    hp[0] = __floats2half2_rn(x0.x, x0.y);
    hp[1] = __floats2half2_rn(x0.z, x0.w);
    hp[2] = __floats2half2_rn(x1.x, x1.y);
    hp[3] = __floats2half2_rn(x1.z, x1.w);
    *(uint2*)(g_ph + rowb + tid * 4) = make_uint2(u.x, u.y);
    *(uint2*)(g_ph + rowb + 1024 + tid * 4) = make_uint2(u.z, u.w);
}

// ---------------------------------------------------------------------------
// Kernel 4: ctx = P @ V, now 3-stage cp.async pipeline.
// ---------------------------------------------------------------------------
#define PVS_PH 0
#define PVS_VH 16384
#define PVS_STRIDE 24576
#define PV_SMEM (3 * PVS_STRIDE)

__global__ __launch_bounds__(256) void pv_mma_kernel(float* __restrict__ ctx)
{
    extern __shared__ char smem[];
    const uint32_t sb = smem_u32(smem);
    const int tid = threadIdx.x, wid = tid >> 5, lane = tid & 31;
    const int z = blockIdx.y;
    const int l0 = blockIdx.x * 128;
    const int m0 = (wid >> 1) * 32, d0 = (wid & 1) * 32;

    const size_t pbase = ((size_t)z * SS + l0) * SS;
    const size_t vbase = (size_t)z * SS * HD;

    auto fill = [&](int s, int rt) {
        const uint32_t stg = sb + s * PVS_STRIDE;
#pragma unroll
        for (int j = 0; j < 4; j++) {
            int idx = tid + 256 * j;
            int row = idx >> 3, c = idx & 7;
            uint32_t so = SW128((uint32_t)(row * 128 + c * 16));
            cp16(stg + PVS_PH + so, g_ph + pbase + (size_t)row * SS + rt * 64 + c * 8);
        }
#pragma unroll
        for (int j = 0; j < 2; j++) {
            int idx = tid + 256 * j;
            int row = idx >> 3, c = idx & 7;
            uint32_t so = SW128((uint32_t)(row * 128 + c * 16));
            cp16(stg + PVS_VH + so, g_vh + vbase + (size_t)(rt * 64 + row) * HD + c * 8);
        }
        asm volatile("cp.async.commit_group;" ::: "memory");
    };

    float acc[2][4][4];
#pragma unroll
    for (int i = 0; i < 2; i++)
#pragma unroll
        for (int j = 0; j < 4; j++)
#pragma unroll
            for (int c = 0; c < 4; c++) acc[i][j][c] = 0.f;

    const int aRow = lane & 15;
    const int aBx = (lane >> 4) * 16;

    fill(0, 0);
    fill(1, 1);
    fill(2, 2);

    int buf = 0;
    for (int rt = 0; rt < 32; rt++) {
        if (rt < 30)      asm volatile("cp.async.wait_group 2;" ::: "memory");
        else if (rt < 31) asm volatile("cp.async.wait_group 1;" ::: "memory");
        else              asm volatile("cp.async.wait_group 0;" ::: "memory");
        __syncthreads();

        const uint32_t stg = sb + buf * PVS_STRIDE;
#pragma unroll
        for (int ks = 0; ks < 4; ks++) {
            const int kb = ks * 32;
            uint32_t Af[2][4], Bf[2][4];
#pragma unroll
            for (int mf = 0; mf < 2; mf++)
                ldsm4(Af[mf], stg + PVS_PH +
                      SW128((uint32_t)((m0 + mf * 16 + aRow) * 128 + kb + aBx)));
#pragma unroll
            for (int nt = 0; nt < 2; nt++)
                ldsm4t(Bf[nt], stg + PVS_VH +
                       SW128((uint32_t)((ks * 16 + aRow) * 128 + (d0 + nt * 16) * 2 + aBx)));
#pragma unroll
            for (int mf = 0; mf < 2; mf++)
#pragma unroll
                for (int nf = 0; nf < 4; nf++)
                    mma_f16(acc[mf][nf], Af[mf], &Bf[nf >> 1][(nf & 1) * 2]);
        }
        __syncthreads();
        if (rt + 3 < 32) fill(buf, rt + 3);
        buf = (buf == 2) ? 0 : buf + 1;
    }

    const int b = z / NH, h = z % NH;
    const int r = lane >> 2, c2 = 2 * (lane & 3);
#pragma unroll
    for (int mf = 0; mf < 2; mf++) {
        int l = l0 + m0 + mf * 16 + r;
#pragma unroll
        for (int nf = 0; nf < 4; nf++) {
            int d = d0 + nf * 8 + c2;
            float* o = ctx + ((size_t)b * SS + l) * HH + h * HD + d;
            *(float2*)o = make_float2(acc[mf][nf][0], acc[mf][nf][1]);
            *(float2*)(o + (size_t)8 * HH) = make_float2(acc[mf][nf][2], acc[mf][nf][3]);
        }
    }
}

// ---------------------------------------------------------------------------
extern "C" void kernel_launch(void* const* d_in, const int* in_sizes, int n_in,
                              void* d_out, int out_size)
{
    const float* hidden   = (const float*)d_in[0];
    const float* mask     = (const float*)d_in[1];
    const float* qkv_w    = (const float*)d_in[2];
    const float* qkv_b    = (const float*)d_in[3];
    const float* dist_emb = (const float*)d_in[4];

    float* out = (float*)d_out;
    float* ctx = out;
    float* probs = out + (size_t)BB * SS * HH;

    // 1) fp16 conversions of GEMM inputs + E table
    conv_h_kernel<<<BB * SS * HH / 1024, 256>>>(hidden);
    conv_w_kernel<<<HH * 3 * HH / 1024, 256>>>(qkv_w);
    split_e_kernel<<<(EROWS * HD + 255) / 256, 256>>>(dist_emb);

    // 2) QKV projection on HMMA -> g_qh/g_kh/g_vh
    cudaFuncSetAttribute(qkv_mma_kernel,
                         cudaFuncAttributeMaxDynamicSharedMemorySize, QK_SMEM);
    qkv_mma_kernel<<<dim3(3072 / 128, 4096 / 128), 256, QK_SMEM>>>(qkv_b);

    // 3) persistent warp-MMA scores + online row stats -> raw probs + g_rowstat
    cudaFuncSetAttribute(score_mma_kernel,
                         cudaFuncAttributeMaxDynamicSharedMemorySize, SC_SMEM);
    score_mma_kernel<<<dim3(SS / 64, ZT), 640, SC_SMEM>>>(mask, probs);

    // 4) single-pass normalize -> fp32 probs + fp16 g_ph
    normalize_kernel<<<ZT * SS, 256>>>(probs);

    // 5) ctx = probs @ v
    cudaFuncSetAttribute(pv_mma_kernel,
                         cudaFuncAttributeMaxDynamicSharedMemorySize, PV_SMEM);
    pv_mma_kernel<<<dim3(SS / 128, ZT), 256, PV_SMEM>>>(ctx);
}

// round 12
// speedup vs baseline: 3.0878x; 1.2442x over previous
#include <cuda_runtime.h>
#include <cuda_fp16.h>
#include <cstdint>

#define BB 2
#define SS 2048
#define HH 1024
#define NH 16
#define HD 64
#define ZT (BB * NH)
#define EROWS 4096   // 4095 used + 1 zero pad row

// fp16 operands
__device__ __half g_qh[ZT * SS * HD], g_kh[ZT * SS * HD], g_vh[ZT * SS * HD];
__device__ __half g_eh[EROWS * HD];
__device__ __half g_ph[(size_t)ZT * SS * SS];   // fp16 probs (normalize -> pv)
// fp16 copies of GEMM inputs
__device__ __half g_h16[BB * SS * HH];          // hidden  [4096][1024]
__device__ __half g_w16[HH * 3 * HH];           // qkv_w   [1024][3072]
// per-row softmax stats: (max, 1/sum)
__device__ float2 g_rowstat[ZT * SS];

#define SW128(o) ((o) ^ (((o) >> 3) & 0x70))

__device__ __forceinline__ uint32_t smem_u32(const void* p) {
    uint32_t a;
    asm("{ .reg .u64 t; cvta.to.shared.u64 t, %1; cvt.u32.u64 %0, t; }"
        : "=r"(a) : "l"(p));
    return a;
}
__device__ __forceinline__ void ldsm4(uint32_t r[4], uint32_t addr) {
    asm volatile("ldmatrix.sync.aligned.m8n8.x4.shared.b16 {%0,%1,%2,%3}, [%4];"
        : "=r"(r[0]), "=r"(r[1]), "=r"(r[2]), "=r"(r[3]) : "r"(addr));
}
__device__ __forceinline__ void ldsm4t(uint32_t r[4], uint32_t addr) {
    asm volatile("ldmatrix.sync.aligned.m8n8.x4.trans.shared.b16 {%0,%1,%2,%3}, [%4];"
        : "=r"(r[0]), "=r"(r[1]), "=r"(r[2]), "=r"(r[3]) : "r"(addr));
}
__device__ __forceinline__ void mma_f16(float c[4], const uint32_t a[4],
                                        const uint32_t b[2]) {
    asm volatile(
        "mma.sync.aligned.m16n8k16.row.col.f32.f16.f16.f32 "
        "{%0,%1,%2,%3}, {%4,%5,%6,%7}, {%8,%9}, {%0,%1,%2,%3};"
        : "+f"(c[0]), "+f"(c[1]), "+f"(c[2]), "+f"(c[3])
        : "r"(a[0]), "r"(a[1]), "r"(a[2]), "r"(a[3]), "r"(b[0]), "r"(b[1]));
}
__device__ __forceinline__ void cp16(uint32_t smem_addr, const void* gptr) {
    asm volatile("cp.async.cg.shared.global [%0], [%1], 16;"
                 :: "r"(smem_addr), "l"(gptr));
}

// ---------------------------------------------------------------------------
// Convert kernels: fp32 -> fp16
// ---------------------------------------------------------------------------
__global__ __launch_bounds__(256) void conv_h_kernel(const float* __restrict__ src)
{
    int i = blockIdx.x * 256 + threadIdx.x;
    float4 v = ((const float4*)src)[i];
    ((__half2*)g_h16)[2 * i] = __floats2half2_rn(v.x, v.y);
    ((__half2*)g_h16)[2 * i + 1] = __floats2half2_rn(v.z, v.w);
}
__global__ __launch_bounds__(256) void conv_w_kernel(const float* __restrict__ src)
{
    int i = blockIdx.x * 256 + threadIdx.x;
    float4 v = ((const float4*)src)[i];
    ((__half2*)g_w16)[2 * i] = __floats2half2_rn(v.x, v.y);
    ((__half2*)g_w16)[2 * i + 1] = __floats2half2_rn(v.z, v.w);
}

// ---------------------------------------------------------------------------
// Kernel 1: QKV projection on HMMA (unchanged from R8, verified 79us).
// ---------------------------------------------------------------------------
#define QKO_A 0
#define QKO_W 32768
#define QK_SMEM 65536

__global__ __launch_bounds__(256, 2) void qkv_mma_kernel(
    const float* __restrict__ bias)
{
    extern __shared__ char smem[];
    const uint32_t sb = smem_u32(smem);
    const int tid = threadIdx.x, wid = tid >> 5, lane = tid & 31;
    const int bx = blockIdx.x, by = blockIdx.y;
    const int m0 = (wid >> 1) * 32;
    const int wx = wid & 1;

    auto fill = [&](int s, int kt) {
        const uint32_t stgA = sb + QKO_A + s * 16384;
        const uint32_t stgW = sb + QKO_W + s * 16384;
#pragma unroll
        for (int j = 0; j < 4; j++) {
            int idx = tid + 256 * j;
            int row = idx >> 3, c = idx & 7;
            cp16(stgA + SW128((uint32_t)(row * 128 + c * 16)),
                 g_h16 + (size_t)(by * 128 + row) * HH + kt * 64 + c * 8);
        }
#pragma unroll
        for (int j = 0; j < 4; j++) {
            int idx = tid + 256 * j;
            int row = idx >> 4, c = idx & 15;
            cp16(stgW + (c >> 3) * 8192 + SW128((uint32_t)(row * 128 + (c & 7) * 16)),
                 g_w16 + (size_t)(kt * 64 + row) * 3072 + bx * 128 + c * 8);
        }
        asm volatile("cp.async.commit_group;" ::: "memory");
    };

    float acc[2][8][4];
#pragma unroll
    for (int i = 0; i < 2; i++)
#pragma unroll
        for (int j = 0; j < 8; j++)
#pragma unroll
            for (int c = 0; c < 4; c++) acc[i][j][c] = 0.f;

    const int aRow = lane & 15;
    const int aBx = (lane >> 4) * 16;

    fill(0, 0);
    fill(1, 1);

    for (int kt = 0; kt < 16; kt++) {
        if (kt < 15) asm volatile("cp.async.wait_group 1;" ::: "memory");
        else         asm volatile("cp.async.wait_group 0;" ::: "memory");
        __syncthreads();

        const uint32_t stgA = sb + QKO_A + (kt & 1) * 16384;
        const uint32_t wsub = sb + QKO_W + (kt & 1) * 16384 + wx * 8192;
#pragma unroll
        for (int ks = 0; ks < 4; ks++) {
            uint32_t Af[2][4], Bf[4][4];
#pragma unroll
            for (int mf = 0; mf < 2; mf++)
                ldsm4(Af[mf], stgA +
                      SW128((uint32_t)((m0 + mf * 16 + aRow) * 128 + ks * 32 + aBx)));
#pragma unroll
            for (int nt = 0; nt < 4; nt++)
                ldsm4t(Bf[nt], wsub +
                       SW128((uint32_t)((ks * 16 + aRow) * 128 + nt * 32 + aBx)));
#pragma unroll
            for (int mf = 0; mf < 2; mf++)
#pragma unroll
                for (int nf = 0; nf < 8; nf++)
                    mma_f16(acc[mf][nf], Af[mf], &Bf[nf >> 1][(nf & 1) * 2]);
        }
        __syncthreads();
        if (kt + 2 < 16) fill(kt & 1, kt + 2);
    }

    const int r = lane >> 2, c2 = 2 * (lane & 3);
#pragma unroll
    for (int nf = 0; nf < 8; nf++) {
        int n = bx * 128 + wx * 64 + nf * 8 + c2;
        float b0 = bias[n], b1 = bias[n + 1];
        int which = n >> 10;
        int h = (n & 1023) >> 6;
        int d = n & 63;
        __half* dst = (which == 0) ? g_qh : (which == 1) ? g_kh : g_vh;
#pragma unroll
        for (int mf = 0; mf < 2; mf++) {
            int m = by * 128 + m0 + mf * 16 + r;
            int b = m >> 11, s = m & 2047;
            size_t off = ((size_t)(b * NH + h) * SS + s) * HD + d;
            *(__half2*)(dst + off) =
                __floats2half2_rn(acc[mf][nf][0] + b0, acc[mf][nf][1] + b1);
            *(__half2*)(dst + off + (size_t)8 * HD) =
                __floats2half2_rn(acc[mf][nf][2] + b0, acc[mf][nf][3] + b1);
        }
    }
}

// ---------------------------------------------------------------------------
// Kernel 1b: dist_emb -> fp16 (row 4095 zero-padded)
// ---------------------------------------------------------------------------
__global__ __launch_bounds__(256) void split_e_kernel(const float* __restrict__ dist_emb)
{
    int i = blockIdx.x * 256 + threadIdx.x;
    if (i >= EROWS * HD) return;
    float e = (i < 4095 * HD) ? dist_emb[i] : 0.f;
    g_eh[i] = __float2half_rn(e);
}

// ---------------------------------------------------------------------------
// Kernel 2: persistent score kernel, 32-l-row tiles, 384 thr, 2 CTAs/SM.
// Per r-tile (64 cols): S[32x64]=Q@K^T, QE[32x96]=Q@E^T, KE[64x96]=K@E^T.
// 12 warps: w0-4 A=Q (w0,1: B=K; w2-4: B=E), w5-10 A=K B=E, w11 idle in MMA.
// QE/KE staged fp16 (bias magnitude ~0.1 -> ~5e-5 abs error, negligible).
// Online per-row (max, expsum) in gather threads -> g_rowstat.
// ---------------------------------------------------------------------------
#define SCQ 0            // 4096
#define SCK 4096         // 2 x 8192  -> 20480
#define SCE 20480        // 2 x 12288 -> 45056
#define SCS 45056        // 32*68*4 = 8704 -> 53760
#define SCQE 53760       // 32*104*2 = 6656 -> 60416
#define SCKE 60416       // 64*104*2 = 13312 -> 73728
#define SCMASK 73728     // 8192 -> 81920
#define SC_SMEM 81920

__global__ __launch_bounds__(384, 2) void score_mma_kernel(
    const float* __restrict__ mask, float* __restrict__ probs)
{
    extern __shared__ char smem[];
    const uint32_t sb = smem_u32(smem);
    const int tid = threadIdx.x, wid = tid >> 5, lane = tid & 31;
    const int l0 = blockIdx.x * 32;
    const int z = blockIdx.y;

    // prologue: mask row + Q tile
    for (int i = tid; i < 512; i += 384)
        ((float4*)(smem + SCMASK))[i] =
            ((const float4*)(mask + (size_t)(z / NH) * SS))[i];
    if (tid < 256) {
        int row = tid >> 3, c = tid & 7;
        uint32_t so = SW128((uint32_t)(row * 128 + c * 16));
        *(uint4*)(smem + SCQ + so) =
            *(const uint4*)(g_qh + ((size_t)z * SS + l0 + row) * HD + c * 8);
    }

    auto fill = [&](int s, int rt) {
        const uint32_t kbuf = sb + SCK + s * 8192;
        const uint32_t ebuf = sb + SCE + s * 12288;
        const int base2 = l0 - rt * 64 + 1984;
        for (int i = tid; i < 1280; i += 384) {
            if (i < 512) {
                int row = i >> 3, c = i & 7;
                cp16(kbuf + SW128((uint32_t)(row * 128 + c * 16)),
                     g_kh + ((size_t)z * SS + rt * 64 + row) * HD + c * 8);
            } else {
                int j = i - 512;
                int row = j >> 3, c = j & 7;   // row 0..95
                cp16(ebuf + SW128((uint32_t)(row * 128 + c * 16)),
                     g_eh + (size_t)(base2 + row) * HD + c * 8);
            }
        }
        asm volatile("cp.async.commit_group;" ::: "memory");
    };

    fill(0, 0);
    fill(1, 1);

    // warp roles
    const bool mma_act = (wid < 11);
    const bool aIsQ = (wid < 5);
    const int m0 = aIsQ ? 0 : ((wid - 5) & 1) * 32;
    const bool bIsK = (wid < 2);
    const int bn0 = (wid < 2) ? wid * 32
                  : (wid < 5) ? (wid - 2) * 32
                  : ((wid - 5) >> 1) * 32;

    const int aRow = lane & 15;
    const int aBx = (lane >> 4) * 16;
    const int bRow = (lane & 7) + (lane >> 4) * 8;
    const int bBx = ((lane >> 3) & 1) * 16;

    // online softmax state (gather threads: tid < 256)
    float om = -1e30f, os = 0.f;

    for (int r0 = 0; r0 < 32; r0++) {
        if (r0 < 31) asm volatile("cp.async.wait_group 1;" ::: "memory");
        else         asm volatile("cp.async.wait_group 0;" ::: "memory");
        __syncthreads();

        const int cur = r0 & 1;
        const uint32_t kbuf = sb + SCK + cur * 8192;
        const uint32_t ebuf = sb + SCE + cur * 12288;

        if (mma_act) {
            const uint32_t aBase = aIsQ ? (sb + SCQ) : kbuf;
            const uint32_t bBase = bIsK ? kbuf : ebuf;

            float acc[2][4][4];
#pragma unroll
            for (int i = 0; i < 2; i++)
#pragma unroll
                for (int j = 0; j < 4; j++)
#pragma unroll
                    for (int c = 0; c < 4; c++) acc[i][j][c] = 0.f;

#pragma unroll
            for (int ks = 0; ks < 4; ks++) {
                const int kb = ks * 32;
                uint32_t Af[2][4], Bf[2][4];
#pragma unroll
                for (int mf = 0; mf < 2; mf++)
                    ldsm4(Af[mf], aBase +
                          SW128((uint32_t)((m0 + mf * 16 + aRow) * 128 + kb + aBx)));
#pragma unroll
                for (int nt = 0; nt < 2; nt++)
                    ldsm4(Bf[nt], bBase +
                          SW128((uint32_t)((bn0 + nt * 16 + bRow) * 128 + kb + bBx)));
#pragma unroll
                for (int mf = 0; mf < 2; mf++)
#pragma unroll
                    for (int nf = 0; nf < 4; nf++)
                        mma_f16(acc[mf][nf], Af[mf], &Bf[nf >> 1][(nf & 1) * 2]);
            }

            // stage
            const int r = lane >> 2, c2 = 2 * (lane & 3);
            if (bIsK) {
                // S: fp32 [32][68]
                float* sp = (float*)(smem + SCS);
#pragma unroll
                for (int mf = 0; mf < 2; mf++) {
                    int u = mf * 16 + r;
#pragma unroll
                    for (int nf = 0; nf < 4; nf++) {
                        int cc = bn0 + nf * 8 + c2;
                        *(float2*)&sp[u * 68 + cc] =
                            make_float2(acc[mf][nf][0], acc[mf][nf][1]);
                        *(float2*)&sp[(u + 8) * 68 + cc] =
                            make_float2(acc[mf][nf][2], acc[mf][nf][3]);
                    }
                }
            } else if (aIsQ) {
                // QE: fp16 [32][104]
                __half* sp = (__half*)(smem + SCQE);
#pragma unroll
                for (int mf = 0; mf < 2; mf++) {
                    int u = mf * 16 + r;
#pragma unroll
                    for (int nf = 0; nf < 4; nf++) {
                        int cc = bn0 + nf * 8 + c2;
                        *(__half2*)&sp[u * 104 + cc] =
                            __floats2half2_rn(acc[mf][nf][0], acc[mf][nf][1]);
                        *(__half2*)&sp[(u + 8) * 104 + cc] =
                            __floats2half2_rn(acc[mf][nf][2], acc[mf][nf][3]);
                    }
                }
            } else {
                // KE: fp16 [64][104]
                __half* sp = (__half*)(smem + SCKE);
#pragma unroll
                for (int mf = 0; mf < 2; mf++) {
                    int v = m0 + mf * 16 + r;
#pragma unroll
                    for (int nf = 0; nf < 4; nf++) {
                        int cc = bn0 + nf * 8 + c2;
                        *(__half2*)&sp[v * 104 + cc] =
                            __floats2half2_rn(acc[mf][nf][0], acc[mf][nf][1]);
                        *(__half2*)&sp[(v + 8) * 104 + cc] =
                            __floats2half2_rn(acc[mf][nf][2], acc[mf][nf][3]);
                    }
                }
            }
        }
        __syncthreads();

        if (r0 + 2 < 32) fill(cur, r0 + 2);

        // gather + online stats + raw-score write
        if (tid < 256) {
            const float* Ss  = (const float*)(smem + SCS);
            const __half* QEs = (const __half*)(smem + SCQE);
            const __half* KEs = (const __half*)(smem + SCKE);
            const float* msk = (const float*)(smem + SCMASK);
            const int u = tid >> 3;
            const int v0 = (tid & 7) * 8;
            float* orow = probs + ((size_t)z * SS + l0 + u) * SS + r0 * 64;

            float4 o[2];
#pragma unroll
            for (int g = 0; g < 2; g++) {
                float* po = (float*)&o[g];
#pragma unroll
                for (int c = 0; c < 4; c++) {
                    int v = v0 + g * 4 + c;
                    int j = u - v + 63;
                    po[c] = 0.125f * Ss[u * 68 + v]
                          + __half2float(QEs[u * 104 + j])
                          + __half2float(KEs[v * 104 + j])
                          + msk[r0 * 64 + v];
                }
            }
            float tm = fmaxf(fmaxf(fmaxf(o[0].x, o[0].y), fmaxf(o[0].z, o[0].w)),
                             fmaxf(fmaxf(o[1].x, o[1].y), fmaxf(o[1].z, o[1].w)));
            float mn = fmaxf(om, tm);
            float add = __expf(o[0].x - mn) + __expf(o[0].y - mn)
                      + __expf(o[0].z - mn) + __expf(o[0].w - mn)
                      + __expf(o[1].x - mn) + __expf(o[1].y - mn)
                      + __expf(o[1].z - mn) + __expf(o[1].w - mn);
            os = os * __expf(om - mn) + add;
            om = mn;

            *(float4*)(orow + v0) = o[0];
            *(float4*)(orow + v0 + 4) = o[1];
        }
    }

    // combine stats per row (8 lanes per row) and store
    if (tid < 256) {
#pragma unroll
        for (int d = 4; d > 0; d >>= 1) {
            float m2 = __shfl_xor_sync(0xFFFFFFFF, om, d);
            float s2 = __shfl_xor_sync(0xFFFFFFFF, os, d);
            float mn = fmaxf(om, m2);
            os = os * __expf(om - mn) + s2 * __expf(m2 - mn);
            om = mn;
        }
        if ((tid & 7) == 0)
            g_rowstat[(size_t)z * SS + l0 + (tid >> 3)] = make_float2(om, 1.f / os);
    }
}

// ---------------------------------------------------------------------------
// Kernel 3: single-pass normalize (unchanged from R11).
// ---------------------------------------------------------------------------
__global__ __launch_bounds__(256) void normalize_kernel(float* __restrict__ probs)
{
    const int tid = threadIdx.x;
    const size_t row = blockIdx.x;
    const size_t rowb = row * SS;
    const float2 st = g_rowstat[row];
    const float m = st.x, inv = st.y;

    float4* p = (float4*)(probs + rowb);
    float4 x0 = p[tid];
    float4 x1 = p[tid + 256];

    x0.x = __expf(x0.x - m) * inv; x0.y = __expf(x0.y - m) * inv;
    x0.z = __expf(x0.z - m) * inv; x0.w = __expf(x0.w - m) * inv;
    x1.x = __expf(x1.x - m) * inv; x1.y = __expf(x1.y - m) * inv;
    x1.z = __expf(x1.z - m) * inv; x1.w = __expf(x1.w - m) * inv;

    p[tid] = x0;
    p[tid + 256] = x1;

    uint4 u;
    __half2* hp = (__half2*)&u;
    hp[0] = __floats2half2_rn(x0.x, x0.y);
    hp[1] = __floats2half2_rn(x0.z, x0.w);
    hp[2] = __floats2half2_rn(x1.x, x1.y);
    hp[3] = __floats2half2_rn(x1.z, x1.w);
    *(uint2*)(g_ph + rowb + tid * 4) = make_uint2(u.x, u.y);
    *(uint2*)(g_ph + rowb + 1024 + tid * 4) = make_uint2(u.z, u.w);
}

// ---------------------------------------------------------------------------
// Kernel 4: ctx = P @ V, 3-stage cp.async pipeline (unchanged from R11).
// ---------------------------------------------------------------------------
#define PVS_PH 0
#define PVS_VH 16384
#define PVS_STRIDE 24576
#define PV_SMEM (3 * PVS_STRIDE)

__global__ __launch_bounds__(256) void pv_mma_kernel(float* __restrict__ ctx)
{
    extern __shared__ char smem[];
    const uint32_t sb = smem_u32(smem);
    const int tid = threadIdx.x, wid = tid >> 5, lane = tid & 31;
    const int z = blockIdx.y;
    const int l0 = blockIdx.x * 128;
    const int m0 = (wid >> 1) * 32, d0 = (wid & 1) * 32;

    const size_t pbase = ((size_t)z * SS + l0) * SS;
    const size_t vbase = (size_t)z * SS * HD;

    auto fill = [&](int s, int rt) {
        const uint32_t stg = sb + s * PVS_STRIDE;
#pragma unroll
        for (int j = 0; j < 4; j++) {
            int idx = tid + 256 * j;
            int row = idx >> 3, c = idx & 7;
            uint32_t so = SW128((uint32_t)(row * 128 + c * 16));
            cp16(stg + PVS_PH + so, g_ph + pbase + (size_t)row * SS + rt * 64 + c * 8);
        }
#pragma unroll
        for (int j = 0; j < 2; j++) {
            int idx = tid + 256 * j;
            int row = idx >> 3, c = idx & 7;
            uint32_t so = SW128((uint32_t)(row * 128 + c * 16));
            cp16(stg + PVS_VH + so, g_vh + vbase + (size_t)(rt * 64 + row) * HD + c * 8);
        }
        asm volatile("cp.async.commit_group;" ::: "memory");
    };

    float acc[2][4][4];
#pragma unroll
    for (int i = 0; i < 2; i++)
#pragma unroll
        for (int j = 0; j < 4; j++)
#pragma unroll
            for (int c = 0; c < 4; c++) acc[i][j][c] = 0.f;

    const int aRow = lane & 15;
    const int aBx = (lane >> 4) * 16;

    fill(0, 0);
    fill(1, 1);
    fill(2, 2);

    int buf = 0;
    for (int rt = 0; rt < 32; rt++) {
        if (rt < 30)      asm volatile("cp.async.wait_group 2;" ::: "memory");
        else if (rt < 31) asm volatile("cp.async.wait_group 1;" ::: "memory");
        else              asm volatile("cp.async.wait_group 0;" ::: "memory");
        __syncthreads();

        const uint32_t stg = sb + buf * PVS_STRIDE;
#pragma unroll
        for (int ks = 0; ks < 4; ks++) {
            const int kb = ks * 32;
            uint32_t Af[2][4], Bf[2][4];
#pragma unroll
            for (int mf = 0; mf < 2; mf++)
                ldsm4(Af[mf], stg + PVS_PH +
                      SW128((uint32_t)((m0 + mf * 16 + aRow) * 128 + kb + aBx)));
#pragma unroll
            for (int nt = 0; nt < 2; nt++)
                ldsm4t(Bf[nt], stg + PVS_VH +
                       SW128((uint32_t)((ks * 16 + aRow) * 128 + (d0 + nt * 16) * 2 + aBx)));
#pragma unroll
            for (int mf = 0; mf < 2; mf++)
#pragma unroll
                for (int nf = 0; nf < 4; nf++)
                    mma_f16(acc[mf][nf], Af[mf], &Bf[nf >> 1][(nf & 1) * 2]);
        }
        __syncthreads();
        if (rt + 3 < 32) fill(buf, rt + 3);
        buf = (buf == 2) ? 0 : buf + 1;
    }

    const int b = z / NH, h = z % NH;
    const int r = lane >> 2, c2 = 2 * (lane & 3);
#pragma unroll
    for (int mf = 0; mf < 2; mf++) {
        int l = l0 + m0 + mf * 16 + r;
#pragma unroll
        for (int nf = 0; nf < 4; nf++) {
            int d = d0 + nf * 8 + c2;
            float* o = ctx + ((size_t)b * SS + l) * HH + h * HD + d;
            *(float2*)o = make_float2(acc[mf][nf][0], acc[mf][nf][1]);
            *(float2*)(o + (size_t)8 * HH) = make_float2(acc[mf][nf][2], acc[mf][nf][3]);
        }
    }
}

// ---------------------------------------------------------------------------
extern "C" void kernel_launch(void* const* d_in, const int* in_sizes, int n_in,
                              void* d_out, int out_size)
{
    const float* hidden   = (const float*)d_in[0];
    const float* mask     = (const float*)d_in[1];
    const float* qkv_w    = (const float*)d_in[2];
    const float* qkv_b    = (const float*)d_in[3];
    const float* dist_emb = (const float*)d_in[4];

    float* out = (float*)d_out;
    float* ctx = out;
    float* probs = out + (size_t)BB * SS * HH;

    // 1) fp16 conversions of GEMM inputs + E table
    conv_h_kernel<<<BB * SS * HH / 1024, 256>>>(hidden);
    conv_w_kernel<<<HH * 3 * HH / 1024, 256>>>(qkv_w);
    split_e_kernel<<<(EROWS * HD + 255) / 256, 256>>>(dist_emb);

    // 2) QKV projection on HMMA -> g_qh/g_kh/g_vh
    cudaFuncSetAttribute(qkv_mma_kernel,
                         cudaFuncAttributeMaxDynamicSharedMemorySize, QK_SMEM);
    qkv_mma_kernel<<<dim3(3072 / 128, 4096 / 128), 256, QK_SMEM>>>(qkv_b);

    // 3) persistent warp-MMA scores (32-l tiles, 2 CTAs/SM) -> raw probs + stats
    cudaFuncSetAttribute(score_mma_kernel,
                         cudaFuncAttributeMaxDynamicSharedMemorySize, SC_SMEM);
    score_mma_kernel<<<dim3(SS / 32, ZT), 384, SC_SMEM>>>(mask, probs);

    // 4) single-pass normalize -> fp32 probs + fp16 g_ph
    normalize_kernel<<<ZT * SS, 256>>>(probs);

    // 5) ctx = probs @ v
    cudaFuncSetAttribute(pv_mma_kernel,
                         cudaFuncAttributeMaxDynamicSharedMemorySize, PV_SMEM);
    pv_mma_kernel<<<dim3(SS / 128, ZT), 256, PV_SMEM>>>(ctx);
}

// round 13
// speedup vs baseline: 3.1343x; 1.0151x over previous
#include <cuda_runtime.h>
#include <cuda_fp16.h>
#include <cstdint>

#define BB 2
#define SS 2048
#define HH 1024
#define NH 16
#define HD 64
#define ZT (BB * NH)
#define EROWS 4096   // 4095 used + 1 zero pad row

// fp16 operands
__device__ __half g_qh[ZT * SS * HD], g_kh[ZT * SS * HD], g_vh[ZT * SS * HD];
__device__ __half g_eh[EROWS * HD];
__device__ __half g_ph[(size_t)ZT * SS * SS];   // fp16 probs (normalize -> pv)
// fp16 copies of GEMM inputs
__device__ __half g_h16[BB * SS * HH];          // hidden  [4096][1024]
__device__ __half g_w16[HH * 3 * HH];           // qkv_w   [1024][3072]
// per-row softmax stats: (max, 1/sum)
__device__ float2 g_rowstat[ZT * SS];

#define SW128(o) ((o) ^ (((o) >> 3) & 0x70))

__device__ __forceinline__ uint32_t smem_u32(const void* p) {
    uint32_t a;
    asm("{ .reg .u64 t; cvta.to.shared.u64 t, %1; cvt.u32.u64 %0, t; }"
        : "=r"(a) : "l"(p));
    return a;
}
__device__ __forceinline__ void ldsm4(uint32_t r[4], uint32_t addr) {
    asm volatile("ldmatrix.sync.aligned.m8n8.x4.shared.b16 {%0,%1,%2,%3}, [%4];"
        : "=r"(r[0]), "=r"(r[1]), "=r"(r[2]), "=r"(r[3]) : "r"(addr));
}
__device__ __forceinline__ void ldsm4t(uint32_t r[4], uint32_t addr) {
    asm volatile("ldmatrix.sync.aligned.m8n8.x4.trans.shared.b16 {%0,%1,%2,%3}, [%4];"
        : "=r"(r[0]), "=r"(r[1]), "=r"(r[2]), "=r"(r[3]) : "r"(addr));
}
__device__ __forceinline__ void mma_f16(float c[4], const uint32_t a[4],
                                        const uint32_t b[2]) {
    asm volatile(
        "mma.sync.aligned.m16n8k16.row.col.f32.f16.f16.f32 "
        "{%0,%1,%2,%3}, {%4,%5,%6,%7}, {%8,%9}, {%0,%1,%2,%3};"
        : "+f"(c[0]), "+f"(c[1]), "+f"(c[2]), "+f"(c[3])
        : "r"(a[0]), "r"(a[1]), "r"(a[2]), "r"(a[3]), "r"(b[0]), "r"(b[1]));
}
__device__ __forceinline__ void cp16(uint32_t smem_addr, const void* gptr) {
    asm volatile("cp.async.cg.shared.global [%0], [%1], 16;"
                 :: "r"(smem_addr), "l"(gptr));
}

// ---------------------------------------------------------------------------
// Convert kernels: fp32 -> fp16
// ---------------------------------------------------------------------------
__global__ __launch_bounds__(256) void conv_h_kernel(const float* __restrict__ src)
{
    int i = blockIdx.x * 256 + threadIdx.x;
    float4 v = ((const float4*)src)[i];
    ((__half2*)g_h16)[2 * i] = __floats2half2_rn(v.x, v.y);
    ((__half2*)g_h16)[2 * i + 1] = __floats2half2_rn(v.z, v.w);
}
__global__ __launch_bounds__(256) void conv_w_kernel(const float* __restrict__ src)
{
    int i = blockIdx.x * 256 + threadIdx.x;
    float4 v = ((const float4*)src)[i];
    ((__half2*)g_w16)[2 * i] = __floats2half2_rn(v.x, v.y);
    ((__half2*)g_w16)[2 * i + 1] = __floats2half2_rn(v.z, v.w);
}

// ---------------------------------------------------------------------------
// Kernel 1: QKV projection on HMMA (unchanged from R8, verified 79us).
// ---------------------------------------------------------------------------
#define QKO_A 0
#define QKO_W 32768
#define QK_SMEM 65536

__global__ __launch_bounds__(256, 2) void qkv_mma_kernel(
    const float* __restrict__ bias)
{
    extern __shared__ char smem[];
    const uint32_t sb = smem_u32(smem);
    const int tid = threadIdx.x, wid = tid >> 5, lane = tid & 31;
    const int bx = blockIdx.x, by = blockIdx.y;
    const int m0 = (wid >> 1) * 32;
    const int wx = wid & 1;

    auto fill = [&](int s, int kt) {
        const uint32_t stgA = sb + QKO_A + s * 16384;
        const uint32_t stgW = sb + QKO_W + s * 16384;
#pragma unroll
        for (int j = 0; j < 4; j++) {
            int idx = tid + 256 * j;
            int row = idx >> 3, c = idx & 7;
            cp16(stgA + SW128((uint32_t)(row * 128 + c * 16)),
                 g_h16 + (size_t)(by * 128 + row) * HH + kt * 64 + c * 8);
        }
#pragma unroll
        for (int j = 0; j < 4; j++) {
            int idx = tid + 256 * j;
            int row = idx >> 4, c = idx & 15;
            cp16(stgW + (c >> 3) * 8192 + SW128((uint32_t)(row * 128 + (c & 7) * 16)),
                 g_w16 + (size_t)(kt * 64 + row) * 3072 + bx * 128 + c * 8);
        }
        asm volatile("cp.async.commit_group;" ::: "memory");
    };

    float acc[2][8][4];
#pragma unroll
    for (int i = 0; i < 2; i++)
#pragma unroll
        for (int j = 0; j < 8; j++)
#pragma unroll
            for (int c = 0; c < 4; c++) acc[i][j][c] = 0.f;

    const int aRow = lane & 15;
    const int aBx = (lane >> 4) * 16;

    fill(0, 0);
    fill(1, 1);

    for (int kt = 0; kt < 16; kt++) {
        if (kt < 15) asm volatile("cp.async.wait_group 1;" ::: "memory");
        else         asm volatile("cp.async.wait_group 0;" ::: "memory");
        __syncthreads();

        const uint32_t stgA = sb + QKO_A + (kt & 1) * 16384;
        const uint32_t wsub = sb + QKO_W + (kt & 1) * 16384 + wx * 8192;
#pragma unroll
        for (int ks = 0; ks < 4; ks++) {
            uint32_t Af[2][4], Bf[4][4];
#pragma unroll
            for (int mf = 0; mf < 2; mf++)
                ldsm4(Af[mf], stgA +
                      SW128((uint32_t)((m0 + mf * 16 + aRow) * 128 + ks * 32 + aBx)));
#pragma unroll
            for (int nt = 0; nt < 4; nt++)
                ldsm4t(Bf[nt], wsub +
                       SW128((uint32_t)((ks * 16 + aRow) * 128 + nt * 32 + aBx)));
#pragma unroll
            for (int mf = 0; mf < 2; mf++)
#pragma unroll
                for (int nf = 0; nf < 8; nf++)
                    mma_f16(acc[mf][nf], Af[mf], &Bf[nf >> 1][(nf & 1) * 2]);
        }
        __syncthreads();
        if (kt + 2 < 16) fill(kt & 1, kt + 2);
    }

    const int r = lane >> 2, c2 = 2 * (lane & 3);
#pragma unroll
    for (int nf = 0; nf < 8; nf++) {
        int n = bx * 128 + wx * 64 + nf * 8 + c2;
        float b0 = bias[n], b1 = bias[n + 1];
        int which = n >> 10;
        int h = (n & 1023) >> 6;
        int d = n & 63;
        __half* dst = (which == 0) ? g_qh : (which == 1) ? g_kh : g_vh;
#pragma unroll
        for (int mf = 0; mf < 2; mf++) {
            int m = by * 128 + m0 + mf * 16 + r;
            int b = m >> 11, s = m & 2047;
            size_t off = ((size_t)(b * NH + h) * SS + s) * HD + d;
            *(__half2*)(dst + off) =
                __floats2half2_rn(acc[mf][nf][0] + b0, acc[mf][nf][1] + b1);
            *(__half2*)(dst + off + (size_t)8 * HD) =
                __floats2half2_rn(acc[mf][nf][2] + b0, acc[mf][nf][3] + b1);
        }
    }
}

// ---------------------------------------------------------------------------
// Kernel 1b: dist_emb -> fp16 (row 4095 zero-padded)
// ---------------------------------------------------------------------------
__global__ __launch_bounds__(256) void split_e_kernel(const float* __restrict__ dist_emb)
{
    int i = blockIdx.x * 256 + threadIdx.x;
    if (i >= EROWS * HD) return;
    float e = (i < 4095 * HD) ? dist_emb[i] : 0.f;
    g_eh[i] = __float2half_rn(e);
}

// ---------------------------------------------------------------------------
// Kernel 2: persistent score kernel, 32-l-row tiles, 384 thr, 2 CTAs/SM.
// (unchanged from R12, verified)
// ---------------------------------------------------------------------------
#define SCQ 0
#define SCK 4096
#define SCE 20480
#define SCS 45056
#define SCQE 53760
#define SCKE 60416
#define SCMASK 73728
#define SC_SMEM 81920

__global__ __launch_bounds__(384, 2) void score_mma_kernel(
    const float* __restrict__ mask, float* __restrict__ probs)
{
    extern __shared__ char smem[];
    const uint32_t sb = smem_u32(smem);
    const int tid = threadIdx.x, wid = tid >> 5, lane = tid & 31;
    const int l0 = blockIdx.x * 32;
    const int z = blockIdx.y;

    for (int i = tid; i < 512; i += 384)
        ((float4*)(smem + SCMASK))[i] =
            ((const float4*)(mask + (size_t)(z / NH) * SS))[i];
    if (tid < 256) {
        int row = tid >> 3, c = tid & 7;
        uint32_t so = SW128((uint32_t)(row * 128 + c * 16));
        *(uint4*)(smem + SCQ + so) =
            *(const uint4*)(g_qh + ((size_t)z * SS + l0 + row) * HD + c * 8);
    }

    auto fill = [&](int s, int rt) {
        const uint32_t kbuf = sb + SCK + s * 8192;
        const uint32_t ebuf = sb + SCE + s * 12288;
        const int base2 = l0 - rt * 64 + 1984;
        for (int i = tid; i < 1280; i += 384) {
            if (i < 512) {
                int row = i >> 3, c = i & 7;
                cp16(kbuf + SW128((uint32_t)(row * 128 + c * 16)),
                     g_kh + ((size_t)z * SS + rt * 64 + row) * HD + c * 8);
            } else {
                int j = i - 512;
                int row = j >> 3, c = j & 7;
                cp16(ebuf + SW128((uint32_t)(row * 128 + c * 16)),
                     g_eh + (size_t)(base2 + row) * HD + c * 8);
            }
        }
        asm volatile("cp.async.commit_group;" ::: "memory");
    };

    fill(0, 0);
    fill(1, 1);

    const bool mma_act = (wid < 11);
    const bool aIsQ = (wid < 5);
    const int m0 = aIsQ ? 0 : ((wid - 5) & 1) * 32;
    const bool bIsK = (wid < 2);
    const int bn0 = (wid < 2) ? wid * 32
                  : (wid < 5) ? (wid - 2) * 32
                  : ((wid - 5) >> 1) * 32;

    const int aRow = lane & 15;
    const int aBx = (lane >> 4) * 16;
    const int bRow = (lane & 7) + (lane >> 4) * 8;
    const int bBx = ((lane >> 3) & 1) * 16;

    float om = -1e30f, os = 0.f;

    for (int r0 = 0; r0 < 32; r0++) {
        if (r0 < 31) asm volatile("cp.async.wait_group 1;" ::: "memory");
        else         asm volatile("cp.async.wait_group 0;" ::: "memory");
        __syncthreads();

        const int cur = r0 & 1;
        const uint32_t kbuf = sb + SCK + cur * 8192;
        const uint32_t ebuf = sb + SCE + cur * 12288;

        if (mma_act) {
            const uint32_t aBase = aIsQ ? (sb + SCQ) : kbuf;
            const uint32_t bBase = bIsK ? kbuf : ebuf;

            float acc[2][4][4];
#pragma unroll
            for (int i = 0; i < 2; i++)
#pragma unroll
                for (int j = 0; j < 4; j++)
#pragma unroll
                    for (int c = 0; c < 4; c++) acc[i][j][c] = 0.f;

#pragma unroll
            for (int ks = 0; ks < 4; ks++) {
                const int kb = ks * 32;
                uint32_t Af[2][4], Bf[2][4];
#pragma unroll
                for (int mf = 0; mf < 2; mf++)
                    ldsm4(Af[mf], aBase +
                          SW128((uint32_t)((m0 + mf * 16 + aRow) * 128 + kb + aBx)));
#pragma unroll
                for (int nt = 0; nt < 2; nt++)
                    ldsm4(Bf[nt], bBase +
                          SW128((uint32_t)((bn0 + nt * 16 + bRow) * 128 + kb + bBx)));
#pragma unroll
                for (int mf = 0; mf < 2; mf++)
#pragma unroll
                    for (int nf = 0; nf < 4; nf++)
                        mma_f16(acc[mf][nf], Af[mf], &Bf[nf >> 1][(nf & 1) * 2]);
            }

            const int r = lane >> 2, c2 = 2 * (lane & 3);
            if (bIsK) {
                float* sp = (float*)(smem + SCS);
#pragma unroll
                for (int mf = 0; mf < 2; mf++) {
                    int u = mf * 16 + r;
#pragma unroll
                    for (int nf = 0; nf < 4; nf++) {
                        int cc = bn0 + nf * 8 + c2;
                        *(float2*)&sp[u * 68 + cc] =
                            make_float2(acc[mf][nf][0], acc[mf][nf][1]);
                        *(float2*)&sp[(u + 8) * 68 + cc] =
                            make_float2(acc[mf][nf][2], acc[mf][nf][3]);
                    }
                }
            } else if (aIsQ) {
                __half* sp = (__half*)(smem + SCQE);
#pragma unroll
                for (int mf = 0; mf < 2; mf++) {
                    int u = mf * 16 + r;
#pragma unroll
                    for (int nf = 0; nf < 4; nf++) {
                        int cc = bn0 + nf * 8 + c2;
                        *(__half2*)&sp[u * 104 + cc] =
                            __floats2half2_rn(acc[mf][nf][0], acc[mf][nf][1]);
                        *(__half2*)&sp[(u + 8) * 104 + cc] =
                            __floats2half2_rn(acc[mf][nf][2], acc[mf][nf][3]);
                    }
                }
            } else {
                __half* sp = (__half*)(smem + SCKE);
#pragma unroll
                for (int mf = 0; mf < 2; mf++) {
                    int v = m0 + mf * 16 + r;
#pragma unroll
                    for (int nf = 0; nf < 4; nf++) {
                        int cc = bn0 + nf * 8 + c2;
                        *(__half2*)&sp[v * 104 + cc] =
                            __floats2half2_rn(acc[mf][nf][0], acc[mf][nf][1]);
                        *(__half2*)&sp[(v + 8) * 104 + cc] =
                            __floats2half2_rn(acc[mf][nf][2], acc[mf][nf][3]);
                    }
                }
            }
        }
        __syncthreads();

        if (r0 + 2 < 32) fill(cur, r0 + 2);

        if (tid < 256) {
            const float* Ss  = (const float*)(smem + SCS);
            const __half* QEs = (const __half*)(smem + SCQE);
            const __half* KEs = (const __half*)(smem + SCKE);
            const float* msk = (const float*)(smem + SCMASK);
            const int u = tid >> 3;
            const int v0 = (tid & 7) * 8;
            float* orow = probs + ((size_t)z * SS + l0 + u) * SS + r0 * 64;

            float4 o[2];
#pragma unroll
            for (int g = 0; g < 2; g++) {
                float* po = (float*)&o[g];
#pragma unroll
                for (int c = 0; c < 4; c++) {
                    int v = v0 + g * 4 + c;
                    int j = u - v + 63;
                    po[c] = 0.125f * Ss[u * 68 + v]
                          + __half2float(QEs[u * 104 + j])
                          + __half2float(KEs[v * 104 + j])
                          + msk[r0 * 64 + v];
                }
            }
            float tm = fmaxf(fmaxf(fmaxf(o[0].x, o[0].y), fmaxf(o[0].z, o[0].w)),
                             fmaxf(fmaxf(o[1].x, o[1].y), fmaxf(o[1].z, o[1].w)));
            float mn = fmaxf(om, tm);
            float add = __expf(o[0].x - mn) + __expf(o[0].y - mn)
                      + __expf(o[0].z - mn) + __expf(o[0].w - mn)
                      + __expf(o[1].x - mn) + __expf(o[1].y - mn)
                      + __expf(o[1].z - mn) + __expf(o[1].w - mn);
            os = os * __expf(om - mn) + add;
            om = mn;

            *(float4*)(orow + v0) = o[0];
            *(float4*)(orow + v0 + 4) = o[1];
        }
    }

    if (tid < 256) {
#pragma unroll
        for (int d = 4; d > 0; d >>= 1) {
            float m2 = __shfl_xor_sync(0xFFFFFFFF, om, d);
            float s2 = __shfl_xor_sync(0xFFFFFFFF, os, d);
            float mn = fmaxf(om, m2);
            os = os * __expf(om - mn) + s2 * __expf(m2 - mn);
            om = mn;
        }
        if ((tid & 7) == 0)
            g_rowstat[(size_t)z * SS + l0 + (tid >> 3)] = make_float2(om, 1.f / os);
    }
}

// ---------------------------------------------------------------------------
// Kernel 3: single-pass normalize (unchanged).
// ---------------------------------------------------------------------------
__global__ __launch_bounds__(256) void normalize_kernel(float* __restrict__ probs)
{
    const int tid = threadIdx.x;
    const size_t row = blockIdx.x;
    const size_t rowb = row * SS;
    const float2 st = g_rowstat[row];
    const float m = st.x, inv = st.y;

    float4* p = (float4*)(probs + rowb);
    float4 x0 = p[tid];
    float4 x1 = p[tid + 256];

    x0.x = __expf(x0.x - m) * inv; x0.y = __expf(x0.y - m) * inv;
    x0.z = __expf(x0.z - m) * inv; x0.w = __expf(x0.w - m) * inv;
    x1.x = __expf(x1.x - m) * inv; x1.y = __expf(x1.y - m) * inv;
    x1.z = __expf(x1.z - m) * inv; x1.w = __expf(x1.w - m) * inv;

    p[tid] = x0;
    p[tid + 256] = x1;

    uint4 u;
    __half2* hp = (__half2*)&u;
    hp[0] = __floats2half2_rn(x0.x, x0.y);
    hp[1] = __floats2half2_rn(x0.z, x0.w);
    hp[2] = __floats2half2_rn(x1.x, x1.y);
    hp[3] = __floats2half2_rn(x1.z, x1.w);
    *(uint2*)(g_ph + rowb + tid * 4) = make_uint2(u.x, u.y);
    *(uint2*)(g_ph + rowb + 1024 + tid * 4) = make_uint2(u.z, u.w);
}

// ---------------------------------------------------------------------------
// Kernel 4: ctx = P @ V, k-chunk 128 (2 sub-tiles/stage), 2-stage cp.async.
// Stage: P0 16K | P1 16K | V0 8K | V1 8K = 48K, x2 = 96K -> 2 CTAs/SM.
// 16 iterations (was 32): half the barriers, double MMA per phase.
// ---------------------------------------------------------------------------
#define PVS_P 0            // 2 x 16384 (sub-tiles: cols 0-63, 64-127 of chunk)
#define PVS_V 32768        // 2 x 8192  (sub-tiles: r 0-63, 64-127 of chunk)
#define PVS_STRIDE 49152
#define PV_SMEM (2 * PVS_STRIDE)

__global__ __launch_bounds__(256) void pv_mma_kernel(float* __restrict__ ctx)
{
    extern __shared__ char smem[];
    const uint32_t sb = smem_u32(smem);
    const int tid = threadIdx.x, wid = tid >> 5, lane = tid & 31;
    const int z = blockIdx.y;
    const int l0 = blockIdx.x * 128;
    const int m0 = (wid >> 1) * 32, d0 = (wid & 1) * 32;

    const size_t pbase = ((size_t)z * SS + l0) * SS;
    const size_t vbase = (size_t)z * SS * HD;

    // fill stage s with k-chunk kt (128 r-columns)
    auto fill = [&](int s, int kt) {
        const uint32_t stg = sb + s * PVS_STRIDE;
#pragma unroll
        for (int j = 0; j < 8; j++) {
            int idx = tid + 256 * j;
            int row = idx >> 4, c = idx & 15;          // P: 128 rows x 16 chunks
            cp16(stg + PVS_P + (c >> 3) * 16384 +
                     SW128((uint32_t)(row * 128 + (c & 7) * 16)),
                 g_ph + pbase + (size_t)row * SS + kt * 128 + c * 8);
        }
#pragma unroll
        for (int j = 0; j < 4; j++) {
            int idx = tid + 256 * j;
            int row = idx >> 3, c = idx & 7;           // V: 128 rows x 8 chunks
            cp16(stg + PVS_V + (row >> 6) * 8192 +
                     SW128((uint32_t)((row & 63) * 128 + c * 16)),
                 g_vh + vbase + (size_t)(kt * 128 + row) * HD + c * 8);
        }
        asm volatile("cp.async.commit_group;" ::: "memory");
    };

    float acc[2][4][4];
#pragma unroll
    for (int i = 0; i < 2; i++)
#pragma unroll
        for (int j = 0; j < 4; j++)
#pragma unroll
            for (int c = 0; c < 4; c++) acc[i][j][c] = 0.f;

    const int aRow = lane & 15;
    const int aBx = (lane >> 4) * 16;

    fill(0, 0);
    fill(1, 1);

    for (int rt = 0; rt < 16; rt++) {
        if (rt < 15) asm volatile("cp.async.wait_group 1;" ::: "memory");
        else         asm volatile("cp.async.wait_group 0;" ::: "memory");
        __syncthreads();

        const uint32_t stg = sb + (rt & 1) * PVS_STRIDE;
#pragma unroll
        for (int ksg = 0; ksg < 2; ksg++) {
            const uint32_t psub = stg + PVS_P + ksg * 16384;
            const uint32_t vsub = stg + PVS_V + ksg * 8192;
#pragma unroll
            for (int ks = 0; ks < 4; ks++) {
                const int kb = ks * 32;
                uint32_t Af[2][4], Bf[2][4];
#pragma unroll
                for (int mf = 0; mf < 2; mf++)
                    ldsm4(Af[mf], psub +
                          SW128((uint32_t)((m0 + mf * 16 + aRow) * 128 + kb + aBx)));
#pragma unroll
                for (int nt = 0; nt < 2; nt++)
                    ldsm4t(Bf[nt], vsub +
                           SW128((uint32_t)((ks * 16 + aRow) * 128 + (d0 + nt * 16) * 2 + aBx)));
#pragma unroll
                for (int mf = 0; mf < 2; mf++)
#pragma unroll
                    for (int nf = 0; nf < 4; nf++)
                        mma_f16(acc[mf][nf], Af[mf], &Bf[nf >> 1][(nf & 1) * 2]);
            }
        }
        __syncthreads();
        if (rt + 2 < 16) fill(rt & 1, rt + 2);
    }

    const int b = z / NH, h = z % NH;
    const int r = lane >> 2, c2 = 2 * (lane & 3);
#pragma unroll
    for (int mf = 0; mf < 2; mf++) {
        int l = l0 + m0 + mf * 16 + r;
#pragma unroll
        for (int nf = 0; nf < 4; nf++) {
            int d = d0 + nf * 8 + c2;
            float* o = ctx + ((size_t)b * SS + l) * HH + h * HD + d;
            *(float2*)o = make_float2(acc[mf][nf][0], acc[mf][nf][1]);
            *(float2*)(o + (size_t)8 * HH) = make_float2(acc[mf][nf][2], acc[mf][nf][3]);
        }
    }
}

// ---------------------------------------------------------------------------
extern "C" void kernel_launch(void* const* d_in, const int* in_sizes, int n_in,
                              void* d_out, int out_size)
{
    const float* hidden   = (const float*)d_in[0];
    const float* mask     = (const float*)d_in[1];
    const float* qkv_w    = (const float*)d_in[2];
    const float* qkv_b    = (const float*)d_in[3];
    const float* dist_emb = (const float*)d_in[4];

    float* out = (float*)d_out;
    float* ctx = out;
    float* probs = out + (size_t)BB * SS * HH;

    // 1) fp16 conversions of GEMM inputs + E table
    conv_h_kernel<<<BB * SS * HH / 1024, 256>>>(hidden);
    conv_w_kernel<<<HH * 3 * HH / 1024, 256>>>(qkv_w);
    split_e_kernel<<<(EROWS * HD + 255) / 256, 256>>>(dist_emb);

    // 2) QKV projection on HMMA -> g_qh/g_kh/g_vh
    cudaFuncSetAttribute(qkv_mma_kernel,
                         cudaFuncAttributeMaxDynamicSharedMemorySize, QK_SMEM);
    qkv_mma_kernel<<<dim3(3072 / 128, 4096 / 128), 256, QK_SMEM>>>(qkv_b);

    // 3) persistent warp-MMA scores (32-l tiles, 2 CTAs/SM) -> raw probs + stats
    cudaFuncSetAttribute(score_mma_kernel,
                         cudaFuncAttributeMaxDynamicSharedMemorySize, SC_SMEM);
    score_mma_kernel<<<dim3(SS / 32, ZT), 384, SC_SMEM>>>(mask, probs);

    // 4) single-pass normalize -> fp32 probs + fp16 g_ph
    normalize_kernel<<<ZT * SS, 256>>>(probs);

    // 5) ctx = probs @ v (k-chunk 128, 2-stage)
    cudaFuncSetAttribute(pv_mma_kernel,
                         cudaFuncAttributeMaxDynamicSharedMemorySize, PV_SMEM);
    pv_mma_kernel<<<dim3(SS / 128, ZT), 256, PV_SMEM>>>(ctx);
}